// round 7
// baseline (speedup 1.0000x reference)
#include <cuda_runtime.h>
#include <cuda_bf16.h>
#include <cstdint>

// Problem constants (fixed by the dataset)
#define B_  2
#define L_  192
#define D_  768
#define NC_ 4
#define H_  256

#define KCH     64              // k per chunk in refine
#define NCHUNK  4               // K = 256 = 4 x 64 (bs tail folded into epilogue)
#define NTHR    256             // refine threads (8 warps)
#define ROWB    144             // padded row stride: 64 bf16 = 128B + 16B pad

#define WIMG_BYTES (256 * ROWB) // one W half-image: 256 n-rows x 144B

// Refine SMEM layout (byte offsets into dynamic smem)
#define OXB(buf)  ((buf) * 36864)            // X buf: XH at +0, XL at +18432
#define OWB(buf)  (73728 + (buf) * 73728)    // W buf: WH at +0, WL at +36864
#define OBMID     221184
#define OWOUT     222208
#define OWTAIL    223232                      // float[4][256]
#define OPART     227328                      // float[128][4]
#define SMEM_BYTES 229376

#define PROJ_BLOCKS 120   // 6 m-tiles x 20 n-tiles
#define PREP_BLOCKS (PROJ_BLOCKS + 32)

// Scratch (no cudaMalloc allowed)
__device__ float g_hp[B_ * L_ * H_];                 // [B*L, H]
__device__ float g_ha[B_ * L_ * NC_ * H_];           // [B*L, NC*H]
__device__ __align__(16) char g_w_img[NC_ * NCHUNK * 2 * WIMG_BYTES];

// ---------------------------------------------------------------------------
// Helpers
// ---------------------------------------------------------------------------
// Rational tanh (Eigen-style): 1 MUFU (rcp) + ~11 FMA, accurate to ~1e-7.
__device__ __forceinline__ float fast_tanh(float x) {
    x = fminf(fmaxf(x, -7.90531110763549805f), 7.90531110763549805f);
    const float s = x * x;
    float p = fmaf(s, -2.76076847742355e-16f, 2.00018790482477e-13f);
    p = fmaf(p, s, -8.60467152213735e-11f);
    p = fmaf(p, s, 5.12229709037114e-08f);
    p = fmaf(p, s, 1.48572235717979e-05f);
    p = fmaf(p, s, 6.37261928875436e-04f);
    p = fmaf(p, s, 4.89352455891786e-03f);
    float q = fmaf(s, 1.19825839466702e-06f, 1.18534705686654e-04f);
    q = fmaf(q, s, 2.26843463243900e-03f);
    q = fmaf(q, s, 4.89352518554385e-03f);
    return __fdividef(x * p, q);
}

__device__ __forceinline__ uint32_t bf16pack(float a, float b) {
    uint32_t r;
    asm("cvt.rn.bf16x2.f32 %0, %1, %2;" : "=r"(r) : "f"(b), "f"(a));
    return r;
}
__device__ __forceinline__ float bf_lo(uint32_t u) { return __uint_as_float(u << 16); }
__device__ __forceinline__ float bf_hi(uint32_t u) { return __uint_as_float(u & 0xFFFF0000u); }

__device__ __forceinline__ unsigned long long pack2(float x) {
    unsigned long long r;
    asm("mov.b64 %0, {%1, %1};" : "=l"(r) : "f"(x));
    return r;
}
__device__ __forceinline__ unsigned long long ffma2(unsigned long long a,
                                                    unsigned long long b,
                                                    unsigned long long c) {
    unsigned long long d;
    asm("fma.rn.f32x2 %0, %1, %2, %3;" : "=l"(d) : "l"(a), "l"(b), "l"(c));
    return d;
}
__device__ __forceinline__ void unpack2(unsigned long long v, float& lo, float& hi) {
    asm("mov.b64 {%0, %1}, %2;" : "=f"(lo), "=f"(hi) : "l"(v));
}

__device__ __forceinline__ void cp_async16(uint32_t smem, const void* gptr) {
    asm volatile("cp.async.cg.shared.global [%0], [%1], 16;" :: "r"(smem), "l"(gptr));
}
__device__ __forceinline__ void cp_commit() { asm volatile("cp.async.commit_group;"); }
__device__ __forceinline__ void cp_wait_all() { asm volatile("cp.async.wait_group 0;" ::: "memory"); }

__device__ __forceinline__ void sts128(uint32_t addr, uint32_t r0, uint32_t r1,
                                       uint32_t r2, uint32_t r3) {
    asm volatile("st.shared.v4.b32 [%0], {%1, %2, %3, %4};"
                 :: "r"(addr), "r"(r0), "r"(r1), "r"(r2), "r"(r3) : "memory");
}

__device__ __forceinline__ void ldsm4(uint32_t* r, uint32_t addr) {
    asm volatile("ldmatrix.sync.aligned.m8n8.x4.shared.b16 {%0,%1,%2,%3}, [%4];"
                 : "=r"(r[0]), "=r"(r[1]), "=r"(r[2]), "=r"(r[3]) : "r"(addr));
}

__device__ __forceinline__ void mma16816(float* d, const uint32_t* a, const uint32_t* b) {
    asm volatile("mma.sync.aligned.m16n8k16.row.col.f32.bf16.bf16.f32 "
                 "{%0,%1,%2,%3}, {%4,%5,%6,%7}, {%8,%9}, {%0,%1,%2,%3};"
                 : "+f"(d[0]), "+f"(d[1]), "+f"(d[2]), "+f"(d[3])
                 : "r"(a[0]), "r"(a[1]), "r"(a[2]), "r"(a[3]),
                   "r"(b[0]), "r"(b[1]));
}

// ---------------------------------------------------------------------------
// Kernel 1 (fused): proj (blocks 0..119) + wsplit (blocks 120..151)
// proj: h_p = seq@Wp + bp, h_a = seq@Wa + ba. Tile 64x64, KC=32, double-buffered.
// wsplit: Wmid -> bf16 hi/lo images, rows padded to 144B.
// ---------------------------------------------------------------------------
__global__ __launch_bounds__(256) void prep_kernel(
    const float* __restrict__ seq,
    const float* __restrict__ Wp, const float* __restrict__ bp,
    const float* __restrict__ Wa, const float* __restrict__ ba,
    const float* __restrict__ Wmid)
{
    const int tid = threadIdx.x;
    const int bx = blockIdx.x;

    if (bx >= PROJ_BLOCKS) {
        // ---- wsplit part: 32 blocks, each n x chunk x half-of-kp ----
        const int idx = bx - PROJ_BLOCKS;
        const int n = idx >> 3, c = (idx >> 1) & 3, half = idx & 1;
        const int j = tid;
        char* imgH = g_w_img + (size_t)((n * NCHUNK + c) * 2) * WIMG_BYTES;
        char* imgL = imgH + WIMG_BYTES;
#pragma unroll 1
        for (int kp = half * 16; kp < half * 16 + 16; kp++) {
            const int k0 = c * KCH + kp * 2;
            const float w0 = Wmid[(n * (H_ + NC_) + k0    ) * H_ + j];
            const float w1 = Wmid[(n * (H_ + NC_) + k0 + 1) * H_ + j];
            const uint32_t h = bf16pack(w0, w1);
            const uint32_t l = bf16pack(w0 - bf_lo(h), w1 - bf_hi(h));
            *(uint32_t*)(imgH + j * ROWB + kp * 4) = h;
            *(uint32_t*)(imgL + j * ROWB + kp * 4) = l;
        }
        if (half == 0) {  // zero the 16B row pad once
            *(uint4*)(imgH + j * ROWB + 128) = make_uint4(0, 0, 0, 0);
            *(uint4*)(imgL + j * ROWB + 128) = make_uint4(0, 0, 0, 0);
        }
        return;
    }

    // ---- proj part ----
    __shared__ __align__(16) float As[2][32][68];   // [buf][k][m] padded
    __shared__ __align__(16) float Bs[2][32][64];   // [buf][k][n]

    const int tx = tid & 15;        // n micro: cols tx*4
    const int ty = tid >> 4;        // m micro: rows ty*4 (ty 0..15)
    const int m0 = (bx / 20) * 64;
    const int n0 = (bx % 20) * 64;

    const float* Wsrc;
    int ld, coff;
    if (n0 < H_) { Wsrc = Wp; ld = H_;        coff = n0; }
    else         { Wsrc = Wa; ld = NC_ * H_;  coff = n0 - H_; }

    // loader indices
    const int lm = tid >> 3;          // 0..31 (A row group)
    const int lk = (tid & 7) * 4;     // A k-subgroup of 4
    const int br = tid >> 4;          // B rows: 2 per thread via e-loop

    auto copyB = [&](int kc, int buf) {
        const uint32_t dst = (uint32_t)__cvta_generic_to_shared(&Bs[buf][0][0]);
#pragma unroll
        for (int i = 0; i < 2; i++) {
            const int e = i * 256 + tid;          // 512 x 16B
            const int row = e >> 4, c4 = e & 15;
            cp_async16(dst + (uint32_t)(row * 256 + c4 * 16),
                       Wsrc + (size_t)(kc + row) * ld + coff + c4 * 4);
        }
        cp_commit();
    };
    auto ldgA = [&](int kc, float4* a) {
        a[0] = *(const float4*)(seq + (size_t)(m0 + lm) * D_ + kc + lk);
        a[1] = *(const float4*)(seq + (size_t)(m0 + lm + 32) * D_ + kc + lk);
    };
    auto stsA = [&](const float4* a, int buf) {
#pragma unroll
        for (int j = 0; j < 4; j++) {
            As[buf][lk + j][lm] = ((const float*)&a[0])[j];
            As[buf][lk + j][lm + 32] = ((const float*)&a[1])[j];
        }
    };

    unsigned long long acc2[4][2];
#pragma unroll
    for (int i = 0; i < 4; i++) { acc2[i][0] = 0ull; acc2[i][1] = 0ull; }

    float4 areg[2];
    copyB(0, 0);
    ldgA(0, areg);
    stsA(areg, 0);
    cp_wait_all();
    __syncthreads();

#pragma unroll 1
    for (int c = 0; c < 24; c++) {
        const int buf = c & 1;
        if (c < 23) {
            copyB((c + 1) * 32, buf ^ 1);
            ldgA((c + 1) * 32, areg);
        }
#pragma unroll
        for (int k = 0; k < 32; k++) {
            const float4 a4 = *(const float4*)&As[buf][k][ty * 4];
            const ulonglong2 b2 = *(const ulonglong2*)&Bs[buf][k][tx * 4];
            const unsigned long long pa[4] = {pack2(a4.x), pack2(a4.y),
                                              pack2(a4.z), pack2(a4.w)};
#pragma unroll
            for (int i = 0; i < 4; i++) {
                acc2[i][0] = ffma2(pa[i], b2.x, acc2[i][0]);
                acc2[i][1] = ffma2(pa[i], b2.y, acc2[i][1]);
            }
        }
        if (c < 23) {
            stsA(areg, buf ^ 1);
            cp_wait_all();
            __syncthreads();
        }
    }

#pragma unroll
    for (int i = 0; i < 4; i++) {
        const int r = m0 + ty * 4 + i;
#pragma unroll
        for (int j = 0; j < 2; j++) {
            float lo, hi;
            unpack2(acc2[i][j], lo, hi);
            const int cg = n0 + tx * 4 + j * 2;
            if (cg < H_) {
                g_hp[r * H_ + cg] = lo + bp[cg];
                g_hp[r * H_ + cg + 1] = hi + bp[cg + 1];
            } else {
                const int c2 = cg - H_;
                g_ha[r * (NC_ * H_) + c2] = lo + ba[c2];
                g_ha[r * (NC_ * H_) + c2 + 1] = hi + ba[c2 + 1];
            }
        }
    }
}

// ---------------------------------------------------------------------------
// Kernel 2: refinement via mma.sync m16n8k16 bf16 (split hi/lo, 3 terms).
// Block (b, n, 8p x 16a): D[128,256] = X[128,256] @ W[256,256] + bs-tail (epi).
// 256 threads = 8 warps, 2(M) x 4(N), warp tile 64x64.
// ---------------------------------------------------------------------------
__global__ __launch_bounds__(NTHR, 1) void refine_kernel(
    const float* __restrict__ bscore,   // [B, L, NC, L]
    const float* __restrict__ Wmid,     // [NC, H+NC, H]
    const float* __restrict__ bmid,     // [NC, H]
    const float* __restrict__ Wout,     // [NC, H]
    float* __restrict__ out)            // [B, L, NC, L]
{
    extern __shared__ __align__(16) char sm[];
    const uint32_t base = (uint32_t)__cvta_generic_to_shared(sm);

    float* bmid_s  = (float*)(sm + OBMID);
    float* wout_s  = (float*)(sm + OWOUT);
    float* wtail_s = (float*)(sm + OWTAIL);  // [4][256]
    float* part_s  = (float*)(sm + OPART);   // [128][4]

    const int tid = threadIdx.x;
    const int wid = tid >> 5;
    const int lane = tid & 31;
    const int bz = blockIdx.z;
    const int b = bz >> 2, n = bz & 3;
    const int p0 = blockIdx.y * 8;
    const int a0 = blockIdx.x * 16;

    const int mwarp = (wid & 1) * 64;    // 2 M-warps
    const int nwarp = (wid >> 1) * 64;   // 4 N-warps
    const int wn = wid >> 1;

    // epilogue tables
    bmid_s[tid] = bmid[n * H_ + tid];
    bmid_s[tid ^ 128] = bmid[n * H_ + (tid ^ 128)];  // 256 entries w/ 256 thr
    wout_s[tid] = Wout[n * H_ + tid];
    wout_s[tid ^ 128] = Wout[n * H_ + (tid ^ 128)];
#pragma unroll
    for (int q = 0; q < 4; q++) {
        const int i = q * NTHR + tid;
        wtail_s[i] = Wmid[(n * (H_ + NC_) + H_ + (i >> 8)) * H_ + (i & 255)];
    }

    // build-thread mapping: row bm = tid>>1, k-half kq = (tid&1)*32
    const int bm = tid >> 1;
    const int kq = (tid & 1) * 32;
    const int bp_ = p0 + (bm >> 4);
    const int ba_ = a0 + (bm & 15);
    const float* hp_row = g_hp + (b * L_ + bp_) * H_;
    const float* ha_row = g_ha + ((b * L_ + ba_) * NC_ + n) * H_;

    // lane-constant ldmatrix address offsets
    const uint32_t a_off = (uint32_t)((mwarp + (lane & 15)) * ROWB + ((lane >> 4) << 4));
    const uint32_t b_off = (uint32_t)((nwarp + (lane & 7) + ((lane & 16) ? 8 : 0)) * ROWB
                                      + ((lane & 8) ? 16 : 0));

    auto buildX = [&](int c, int buf) {
        const uint32_t xh = base + OXB(buf) + (uint32_t)(bm * ROWB + kq * 2);
        const uint32_t xl = xh + 18432;
        const float4* hp4 = (const float4*)(hp_row + c * KCH + kq);
        const float4* ha4 = (const float4*)(ha_row + c * KCH + kq);
#pragma unroll
        for (int half = 0; half < 2; half++) {      // 2 x 16 k
            uint32_t hw[8], lw[8];
#pragma unroll
            for (int g = 0; g < 4; g++) {
                const float4 u = hp4[half * 4 + g];
                const float4 v = ha4[half * 4 + g];
                const float x0 = fast_tanh(u.x + v.x);
                const float x1 = fast_tanh(u.y + v.y);
                const float x2 = fast_tanh(u.z + v.z);
                const float x3 = fast_tanh(u.w + v.w);
                const uint32_t hA = bf16pack(x0, x1);
                const uint32_t hB = bf16pack(x2, x3);
                hw[g * 2 + 0] = hA;
                hw[g * 2 + 1] = hB;
                lw[g * 2 + 0] = bf16pack(x0 - bf_lo(hA), x1 - bf_hi(hA));
                lw[g * 2 + 1] = bf16pack(x2 - bf_lo(hB), x3 - bf_hi(hB));
            }
            sts128(xh + half * 32,      hw[0], hw[1], hw[2], hw[3]);
            sts128(xh + half * 32 + 16, hw[4], hw[5], hw[6], hw[7]);
            sts128(xl + half * 32,      lw[0], lw[1], lw[2], lw[3]);
            sts128(xl + half * 32 + 16, lw[4], lw[5], lw[6], lw[7]);
        }
    };

    auto copyW = [&](int c, int buf) {
        const char* src = g_w_img + (size_t)((n * NCHUNK + c) * 2) * WIMG_BYTES;
        const uint32_t dst = base + OWB(buf);
#pragma unroll
        for (int i = 0; i < 18; i++) {
            const int e = i * NTHR + tid;
            cp_async16(dst + e * 16, src + (size_t)e * 16);
        }
        cp_commit();
    };

    float acc[4][8][4];
#pragma unroll
    for (int t = 0; t < 4; t++)
#pragma unroll
        for (int q = 0; q < 8; q++)
#pragma unroll
            for (int r = 0; r < 4; r++) acc[t][q][r] = 0.0f;

    // one k16-step: 4 m16 frags (hi+lo) x 8 n8 frags, 3 split terms
    auto mma_ks = [&](int ks, uint32_t xb, uint32_t wb) {
        uint32_t AH[4][4], AL[4][4], Bf[4][4];
        const uint32_t kb = (uint32_t)(ks * 32);
#pragma unroll
        for (int t = 0; t < 4; t++) {
            ldsm4(AH[t], xb + a_off + t * 16 * ROWB + kb);
            ldsm4(AL[t], xb + 18432 + a_off + t * 16 * ROWB + kb);
        }
#pragma unroll
        for (int q = 0; q < 4; q++)
            ldsm4(Bf[q], wb + b_off + q * 16 * ROWB + kb);
        // seg0 (XH*WH) + seg1 (XL*WH)
#pragma unroll
        for (int t = 0; t < 4; t++)
#pragma unroll
            for (int q2 = 0; q2 < 8; q2++) {
                const uint32_t* bq = &Bf[q2 >> 1][(q2 & 1) * 2];
                mma16816(acc[t][q2], AH[t], bq);
                mma16816(acc[t][q2], AL[t], bq);
            }
        // seg2 (XH*WL)
#pragma unroll
        for (int q = 0; q < 4; q++)
            ldsm4(Bf[q], wb + 36864 + b_off + q * 16 * ROWB + kb);
#pragma unroll
        for (int t = 0; t < 4; t++)
#pragma unroll
            for (int q2 = 0; q2 < 8; q2++) {
                const uint32_t* bq = &Bf[q2 >> 1][(q2 & 1) * 2];
                mma16816(acc[t][q2], AH[t], bq);
            }
    };

    // ---- prologue ----
    copyW(0, 0);
    buildX(0, 0);
    cp_wait_all();
    __syncthreads();

#pragma unroll 1
    for (int c = 0; c < NCHUNK; c++) {
        const int cur = c & 1;
        const uint32_t xb = base + OXB(cur);
        const uint32_t wb = base + OWB(cur);
        if (c < NCHUNK - 1) copyW(c + 1, cur ^ 1);
        mma_ks(0, xb, wb);
        mma_ks(1, xb, wb);
        if (c < NCHUNK - 1) buildX(c + 1, cur ^ 1);
        mma_ks(2, xb, wb);
        mma_ks(3, xb, wb);
        if (c < NCHUNK - 1) {
            cp_wait_all();
            __syncthreads();
        }
    }

    // ---- epilogue: +bs-tail +bmid, tanh, dot Wout, reduce over N ----
    const int g = lane >> 2;
    float bsv[4][2][4];     // [t][h][ct]
#pragma unroll
    for (int t = 0; t < 4; t++)
#pragma unroll
        for (int h = 0; h < 2; h++) {
            const int row = mwarp + t * 16 + g + h * 8;
            const float* bsp = bscore
                + ((b * L_ + p0 + (row >> 4)) * NC_) * L_ + a0 + (row & 15);
#pragma unroll
            for (int ct = 0; ct < 4; ct++) bsv[t][h][ct] = bsp[ct * L_];
        }

    float part[4][2];
#pragma unroll
    for (int t = 0; t < 4; t++) { part[t][0] = 0.0f; part[t][1] = 0.0f; }

#pragma unroll
    for (int q2 = 0; q2 < 8; q2++) {
        const int j0 = nwarp + q2 * 8 + (lane & 3) * 2;
        const float bm0 = bmid_s[j0], bm1 = bmid_s[j0 + 1];
        const float wo0 = wout_s[j0], wo1 = wout_s[j0 + 1];
        float wt0[4], wt1[4];
#pragma unroll
        for (int ct = 0; ct < 4; ct++) {
            wt0[ct] = wtail_s[ct * 256 + j0];
            wt1[ct] = wtail_s[ct * 256 + j0 + 1];
        }
#pragma unroll
        for (int t = 0; t < 4; t++)
#pragma unroll
            for (int h = 0; h < 2; h++) {
                float v0 = acc[t][q2][h * 2 + 0] + bm0;
                float v1 = acc[t][q2][h * 2 + 1] + bm1;
#pragma unroll
                for (int ct = 0; ct < 4; ct++) {
                    v0 = fmaf(bsv[t][h][ct], wt0[ct], v0);
                    v1 = fmaf(bsv[t][h][ct], wt1[ct], v1);
                }
                part[t][h] = fmaf(fast_tanh(v0), wo0, part[t][h]);
                part[t][h] = fmaf(fast_tanh(v1), wo1, part[t][h]);
            }
    }
#pragma unroll
    for (int t = 0; t < 4; t++)
#pragma unroll
        for (int h = 0; h < 2; h++) {
            float v = part[t][h];
            v += __shfl_xor_sync(0xFFFFFFFFu, v, 1, 4);
            v += __shfl_xor_sync(0xFFFFFFFFu, v, 2, 4);
            if ((lane & 3) == 0) {
                const int row = mwarp + t * 16 + g + h * 8;
                part_s[row * 4 + wn] = v;
            }
        }
    __syncthreads();

    if (tid < 128) {
        const float s = part_s[tid * 4] + part_s[tid * 4 + 1]
                      + part_s[tid * 4 + 2] + part_s[tid * 4 + 3];
        const int p = p0 + (tid >> 4);
        const int a = a0 + (tid & 15);
        out[((b * L_ + p) * NC_ + n) * L_ + a] = s;
    }
}

// ---------------------------------------------------------------------------
// Launch
// ---------------------------------------------------------------------------
extern "C" void kernel_launch(void* const* d_in, const int* in_sizes, int n_in,
                              void* d_out, int out_size) {
    const float* seq    = (const float*)d_in[0];
    const float* bscore = (const float*)d_in[1];
    const float* Wp     = (const float*)d_in[2];
    const float* bp     = (const float*)d_in[3];
    const float* Wa     = (const float*)d_in[4];
    const float* ba     = (const float*)d_in[5];
    const float* Wmid   = (const float*)d_in[6];
    const float* bmid   = (const float*)d_in[7];
    const float* Wout   = (const float*)d_in[8];
    float* out = (float*)d_out;

    prep_kernel<<<PREP_BLOCKS, 256>>>(seq, Wp, bp, Wa, ba, Wmid);

    cudaFuncSetAttribute(refine_kernel,
                         cudaFuncAttributeMaxDynamicSharedMemorySize, SMEM_BYTES);
    refine_kernel<<<dim3(L_ / 16, L_ / 8, B_ * NC_), NTHR, SMEM_BYTES>>>(
        bscore, Wmid, bmid, Wout, out);
}

// round 8
// speedup vs baseline: 1.0679x; 1.0679x over previous
#include <cuda_runtime.h>
#include <cuda_bf16.h>
#include <cstdint>

// Problem constants (fixed by the dataset)
#define B_  2
#define L_  192
#define D_  768
#define NC_ 4
#define H_  256

#define KCH     64              // k per chunk in refine
#define NCHUNK  4               // K = 256 = 4 x 64 (bs tail folded into epilogue)
#define NTHR    512             // refine threads (16 warps)
#define ROWB    144             // padded row stride: 64 bf16 = 128B + 16B pad

#define WIMG_BYTES (256 * ROWB) // one W half-image: 256 n-rows x 144B

// Refine SMEM layout (byte offsets into dynamic smem)
#define OXB(buf)  ((buf) * 36864)            // X buf: XH at +0, XL at +18432
#define OWB(buf)  (73728 + (buf) * 73728)    // W buf: WH at +0, WL at +36864
#define OBMID     221184
#define OWOUT     222208
#define OWTAIL    223232                      // float[4][256]
#define OPART     227328                      // float[128][4]
#define SMEM_BYTES 229376

#define PROJ_BLOCKS 120   // 6 m-tiles x 20 n-tiles
#define PREP_BLOCKS (PROJ_BLOCKS + 32)

// Scratch (no cudaMalloc allowed)
__device__ float g_hp[B_ * L_ * H_];                 // [B*L, H]
__device__ float g_ha[B_ * L_ * NC_ * H_];           // [B*L, NC*H]
__device__ __align__(16) char g_w_img[NC_ * NCHUNK * 2 * WIMG_BYTES];

// ---------------------------------------------------------------------------
// Helpers
// ---------------------------------------------------------------------------
// Rational tanh: 1 MUFU (rcp) + ~11 FMA, accurate to ~1e-7.
__device__ __forceinline__ float fast_tanh(float x) {
    x = fminf(fmaxf(x, -7.90531110763549805f), 7.90531110763549805f);
    const float s = x * x;
    float p = fmaf(s, -2.76076847742355e-16f, 2.00018790482477e-13f);
    p = fmaf(p, s, -8.60467152213735e-11f);
    p = fmaf(p, s, 5.12229709037114e-08f);
    p = fmaf(p, s, 1.48572235717979e-05f);
    p = fmaf(p, s, 6.37261928875436e-04f);
    p = fmaf(p, s, 4.89352455891786e-03f);
    float q = fmaf(s, 1.19825839466702e-06f, 1.18534705686654e-04f);
    q = fmaf(q, s, 2.26843463243900e-03f);
    q = fmaf(q, s, 4.89352518554385e-03f);
    return __fdividef(x * p, q);
}

__device__ __forceinline__ uint32_t bf16pack(float a, float b) {
    uint32_t r;
    asm("cvt.rn.bf16x2.f32 %0, %1, %2;" : "=r"(r) : "f"(b), "f"(a));
    return r;
}
__device__ __forceinline__ float bf_lo(uint32_t u) { return __uint_as_float(u << 16); }
__device__ __forceinline__ float bf_hi(uint32_t u) { return __uint_as_float(u & 0xFFFF0000u); }

__device__ __forceinline__ unsigned long long pack2(float x) {
    unsigned long long r;
    asm("mov.b64 %0, {%1, %1};" : "=l"(r) : "f"(x));
    return r;
}
__device__ __forceinline__ unsigned long long ffma2(unsigned long long a,
                                                    unsigned long long b,
                                                    unsigned long long c) {
    unsigned long long d;
    asm("fma.rn.f32x2 %0, %1, %2, %3;" : "=l"(d) : "l"(a), "l"(b), "l"(c));
    return d;
}
__device__ __forceinline__ void unpack2(unsigned long long v, float& lo, float& hi) {
    asm("mov.b64 {%0, %1}, %2;" : "=f"(lo), "=f"(hi) : "l"(v));
}

__device__ __forceinline__ void cp_async16(uint32_t smem, const void* gptr) {
    asm volatile("cp.async.cg.shared.global [%0], [%1], 16;" :: "r"(smem), "l"(gptr));
}
__device__ __forceinline__ void cp_commit() { asm volatile("cp.async.commit_group;"); }
__device__ __forceinline__ void cp_wait_all() { asm volatile("cp.async.wait_group 0;" ::: "memory"); }

__device__ __forceinline__ void sts128(uint32_t addr, uint32_t r0, uint32_t r1,
                                       uint32_t r2, uint32_t r3) {
    asm volatile("st.shared.v4.b32 [%0], {%1, %2, %3, %4};"
                 :: "r"(addr), "r"(r0), "r"(r1), "r"(r2), "r"(r3) : "memory");
}

__device__ __forceinline__ void ldsm4(uint32_t* r, uint32_t addr) {
    asm volatile("ldmatrix.sync.aligned.m8n8.x4.shared.b16 {%0,%1,%2,%3}, [%4];"
                 : "=r"(r[0]), "=r"(r[1]), "=r"(r[2]), "=r"(r[3]) : "r"(addr));
}

__device__ __forceinline__ void mma16816(float* d, const uint32_t* a, const uint32_t* b) {
    asm volatile("mma.sync.aligned.m16n8k16.row.col.f32.bf16.bf16.f32 "
                 "{%0,%1,%2,%3}, {%4,%5,%6,%7}, {%8,%9}, {%0,%1,%2,%3};"
                 : "+f"(d[0]), "+f"(d[1]), "+f"(d[2]), "+f"(d[3])
                 : "r"(a[0]), "r"(a[1]), "r"(a[2]), "r"(a[3]),
                   "r"(b[0]), "r"(b[1]));
}

// ---------------------------------------------------------------------------
// Kernel 1 (fused): proj (blocks 0..119) + wsplit (blocks 120..151)
// ---------------------------------------------------------------------------
__global__ __launch_bounds__(256) void prep_kernel(
    const float* __restrict__ seq,
    const float* __restrict__ Wp, const float* __restrict__ bp,
    const float* __restrict__ Wa, const float* __restrict__ ba,
    const float* __restrict__ Wmid)
{
    const int tid = threadIdx.x;
    const int bx = blockIdx.x;

    if (bx >= PROJ_BLOCKS) {
        // ---- wsplit: 32 blocks, each n x chunk x half-of-kp ----
        const int idx = bx - PROJ_BLOCKS;
        const int n = idx >> 3, c = (idx >> 1) & 3, half = idx & 1;
        const int j = tid;
        char* imgH = g_w_img + (size_t)((n * NCHUNK + c) * 2) * WIMG_BYTES;
        char* imgL = imgH + WIMG_BYTES;
#pragma unroll 1
        for (int kp = half * 16; kp < half * 16 + 16; kp++) {
            const int k0 = c * KCH + kp * 2;
            const float w0 = Wmid[(n * (H_ + NC_) + k0    ) * H_ + j];
            const float w1 = Wmid[(n * (H_ + NC_) + k0 + 1) * H_ + j];
            const uint32_t h = bf16pack(w0, w1);
            const uint32_t l = bf16pack(w0 - bf_lo(h), w1 - bf_hi(h));
            *(uint32_t*)(imgH + j * ROWB + kp * 4) = h;
            *(uint32_t*)(imgL + j * ROWB + kp * 4) = l;
        }
        if (half == 0) {
            *(uint4*)(imgH + j * ROWB + 128) = make_uint4(0, 0, 0, 0);
            *(uint4*)(imgL + j * ROWB + 128) = make_uint4(0, 0, 0, 0);
        }
        return;
    }

    // ---- proj: tile 64x64, KC=32, double-buffered ----
    __shared__ __align__(16) float As[2][32][68];   // [buf][k][m] padded
    __shared__ __align__(16) float Bs[2][32][64];   // [buf][k][n]

    const int tx = tid & 15;
    const int ty = tid >> 4;
    const int m0 = (bx / 20) * 64;
    const int n0 = (bx % 20) * 64;

    const float* Wsrc;
    int ld, coff;
    if (n0 < H_) { Wsrc = Wp; ld = H_;        coff = n0; }
    else         { Wsrc = Wa; ld = NC_ * H_;  coff = n0 - H_; }

    const int lm = tid >> 3;
    const int lk = (tid & 7) * 4;

    auto copyB = [&](int kc, int buf) {
        const uint32_t dst = (uint32_t)__cvta_generic_to_shared(&Bs[buf][0][0]);
#pragma unroll
        for (int i = 0; i < 2; i++) {
            const int e = i * 256 + tid;
            const int row = e >> 4, c4 = e & 15;
            cp_async16(dst + (uint32_t)(row * 256 + c4 * 16),
                       Wsrc + (size_t)(kc + row) * ld + coff + c4 * 4);
        }
        cp_commit();
    };
    auto ldgA = [&](int kc, float4* a) {
        a[0] = *(const float4*)(seq + (size_t)(m0 + lm) * D_ + kc + lk);
        a[1] = *(const float4*)(seq + (size_t)(m0 + lm + 32) * D_ + kc + lk);
    };
    auto stsA = [&](const float4* a, int buf) {
#pragma unroll
        for (int j = 0; j < 4; j++) {
            As[buf][lk + j][lm] = ((const float*)&a[0])[j];
            As[buf][lk + j][lm + 32] = ((const float*)&a[1])[j];
        }
    };

    unsigned long long acc2[4][2];
#pragma unroll
    for (int i = 0; i < 4; i++) { acc2[i][0] = 0ull; acc2[i][1] = 0ull; }

    float4 areg[2];
    copyB(0, 0);
    ldgA(0, areg);
    stsA(areg, 0);
    cp_wait_all();
    __syncthreads();

#pragma unroll 1
    for (int c = 0; c < 24; c++) {
        const int buf = c & 1;
        if (c < 23) {
            copyB((c + 1) * 32, buf ^ 1);
            ldgA((c + 1) * 32, areg);
        }
#pragma unroll
        for (int k = 0; k < 32; k++) {
            const float4 a4 = *(const float4*)&As[buf][k][ty * 4];
            const ulonglong2 b2 = *(const ulonglong2*)&Bs[buf][k][tx * 4];
            const unsigned long long pa[4] = {pack2(a4.x), pack2(a4.y),
                                              pack2(a4.z), pack2(a4.w)};
#pragma unroll
            for (int i = 0; i < 4; i++) {
                acc2[i][0] = ffma2(pa[i], b2.x, acc2[i][0]);
                acc2[i][1] = ffma2(pa[i], b2.y, acc2[i][1]);
            }
        }
        if (c < 23) {
            stsA(areg, buf ^ 1);
            cp_wait_all();
            __syncthreads();
        }
    }

#pragma unroll
    for (int i = 0; i < 4; i++) {
        const int r = m0 + ty * 4 + i;
#pragma unroll
        for (int j = 0; j < 2; j++) {
            float lo, hi;
            unpack2(acc2[i][j], lo, hi);
            const int cg = n0 + tx * 4 + j * 2;
            if (cg < H_) {
                g_hp[r * H_ + cg] = lo + bp[cg];
                g_hp[r * H_ + cg + 1] = hi + bp[cg + 1];
            } else {
                const int c2 = cg - H_;
                g_ha[r * (NC_ * H_) + c2] = lo + ba[c2];
                g_ha[r * (NC_ * H_) + c2 + 1] = hi + ba[c2 + 1];
            }
        }
    }
}

// ---------------------------------------------------------------------------
// Kernel 2: refinement via mma.sync m16n8k16 bf16 (split hi/lo, 3 terms).
// Block (b, n, 8p x 16a): D[128,256] = X[128,256] @ W[256,256] + bs-tail (epi).
// 512 threads = 16 warps, 4(M)x4(N), warp tile 32x64.
// Producer staggering: warp group g = (wid>>2)&1 builds k-half g of chunk c+1
// between MMA k-steps, so >=2 warps/SMSP always issue MMAs.
// ---------------------------------------------------------------------------
__global__ __launch_bounds__(NTHR, 1) void refine_kernel(
    const float* __restrict__ bscore,   // [B, L, NC, L]
    const float* __restrict__ Wmid,     // [NC, H+NC, H]
    const float* __restrict__ bmid,     // [NC, H]
    const float* __restrict__ Wout,     // [NC, H]
    float* __restrict__ out)            // [B, L, NC, L]
{
    extern __shared__ __align__(16) char sm[];
    const uint32_t base = (uint32_t)__cvta_generic_to_shared(sm);

    float* bmid_s  = (float*)(sm + OBMID);
    float* wout_s  = (float*)(sm + OWOUT);
    float* wtail_s = (float*)(sm + OWTAIL);  // [4][256]
    float* part_s  = (float*)(sm + OPART);   // [128][4]

    const int tid = threadIdx.x;
    const int wid = tid >> 5;
    const int lane = tid & 31;
    const int bz = blockIdx.z;
    const int b = bz >> 2, n = bz & 3;
    const int p0 = blockIdx.y * 8;
    const int a0 = blockIdx.x * 16;

    const int mwarp = (wid & 3) * 32;
    const int nwarp = (wid >> 2) * 64;

    // producer group: 2 warps of each group per SMSP
    const int group = (wid >> 2) & 1;
    const int widx = (wid & 3) | ((wid & 8) >> 1);   // 0..7 within group
    const int gtid = widx * 32 + lane;               // 0..255 within group

    // epilogue tables
    if (tid < 256) {
        bmid_s[tid] = bmid[n * H_ + tid];
        wout_s[tid] = Wout[n * H_ + tid];
    }
#pragma unroll
    for (int q = 0; q < 2; q++) {
        const int i = q * NTHR + tid;
        wtail_s[i] = Wmid[(n * (H_ + NC_) + H_ + (i >> 8)) * H_ + (i & 255)];
    }

    // build mapping (per group): row bm = gtid>>1, k-sub = (gtid&1)*16
    const int bm = gtid >> 1;
    const int ksub = (gtid & 1) * 16;
    const int bp_ = p0 + (bm >> 4);
    const int ba_ = a0 + (bm & 15);
    const float* hp_row = g_hp + (b * L_ + bp_) * H_;
    const float* ha_row = g_ha + ((b * L_ + ba_) * NC_ + n) * H_;

    // lane-constant ldmatrix address offsets
    const uint32_t a_off = (uint32_t)((mwarp + (lane & 15)) * ROWB + ((lane >> 4) << 4));
    const uint32_t b_off = (uint32_t)((nwarp + (lane & 7) + ((lane & 16) ? 8 : 0)) * ROWB
                                      + ((lane & 8) ? 16 : 0));

    // build 16 k-values of chunk c at k-offset (koff + ksub) into buffer buf
    auto buildX_part = [&](int c, int buf, int koff) {
        const int kq = koff + ksub;
        const uint32_t xh = base + OXB(buf) + (uint32_t)(bm * ROWB + kq * 2);
        const uint32_t xl = xh + 18432;
        const float4* hp4 = (const float4*)(hp_row + c * KCH + kq);
        const float4* ha4 = (const float4*)(ha_row + c * KCH + kq);
        uint32_t hw[8], lw[8];
#pragma unroll
        for (int g = 0; g < 4; g++) {
            const float4 u = hp4[g];
            const float4 v = ha4[g];
            const float x0 = fast_tanh(u.x + v.x);
            const float x1 = fast_tanh(u.y + v.y);
            const float x2 = fast_tanh(u.z + v.z);
            const float x3 = fast_tanh(u.w + v.w);
            const uint32_t hA = bf16pack(x0, x1);
            const uint32_t hB = bf16pack(x2, x3);
            hw[g * 2 + 0] = hA;
            hw[g * 2 + 1] = hB;
            lw[g * 2 + 0] = bf16pack(x0 - bf_lo(hA), x1 - bf_hi(hA));
            lw[g * 2 + 1] = bf16pack(x2 - bf_lo(hB), x3 - bf_hi(hB));
        }
        sts128(xh,      hw[0], hw[1], hw[2], hw[3]);
        sts128(xh + 16, hw[4], hw[5], hw[6], hw[7]);
        sts128(xl,      lw[0], lw[1], lw[2], lw[3]);
        sts128(xl + 16, lw[4], lw[5], lw[6], lw[7]);
    };

    auto copyW = [&](int c, int buf) {
        const char* src = g_w_img + (size_t)((n * NCHUNK + c) * 2) * WIMG_BYTES;
        const uint32_t dst = base + OWB(buf);
#pragma unroll
        for (int i = 0; i < 9; i++) {
            const int e = i * NTHR + tid;
            cp_async16(dst + e * 16, src + (size_t)e * 16);
        }
        cp_commit();
    };

    float acc[2][8][4];
#pragma unroll
    for (int t = 0; t < 2; t++)
#pragma unroll
        for (int q = 0; q < 8; q++)
#pragma unroll
            for (int r = 0; r < 4; r++) acc[t][q][r] = 0.0f;

    // one k16-step: shared fragments across the 3 split terms
    auto mma_ks = [&](int ks, uint32_t xb, uint32_t wb) {
        uint32_t AH0[4], AH1[4], AL0[4], AL1[4], Bf[4][4];
        const uint32_t kb = (uint32_t)(ks * 32);
        ldsm4(AH0, xb + a_off + kb);
        ldsm4(AH1, xb + a_off + 16 * ROWB + kb);
        ldsm4(AL0, xb + 18432 + a_off + kb);
        ldsm4(AL1, xb + 18432 + a_off + 16 * ROWB + kb);
#pragma unroll
        for (int q = 0; q < 4; q++)
            ldsm4(Bf[q], wb + b_off + q * 16 * ROWB + kb);
        // seg0 (XH*WH) + seg1 (XL*WH)
#pragma unroll
        for (int q2 = 0; q2 < 8; q2++) {
            const uint32_t* bq = &Bf[q2 >> 1][(q2 & 1) * 2];
            mma16816(acc[0][q2], AH0, bq);
            mma16816(acc[1][q2], AH1, bq);
            mma16816(acc[0][q2], AL0, bq);
            mma16816(acc[1][q2], AL1, bq);
        }
        // seg2 (XH*WL)
#pragma unroll
        for (int q = 0; q < 4; q++)
            ldsm4(Bf[q], wb + 36864 + b_off + q * 16 * ROWB + kb);
#pragma unroll
        for (int q2 = 0; q2 < 8; q2++) {
            const uint32_t* bq = &Bf[q2 >> 1][(q2 & 1) * 2];
            mma16816(acc[0][q2], AH0, bq);
            mma16816(acc[1][q2], AH1, bq);
        }
    };

    // ---- prologue: both groups build their half of chunk 0 ----
    copyW(0, 0);
    buildX_part(0, 0, group * 32);
    cp_wait_all();
    __syncthreads();

#pragma unroll 1
    for (int c = 0; c < NCHUNK; c++) {
        const int cur = c & 1;
        const uint32_t xb = base + OXB(cur);
        const uint32_t wb = base + OWB(cur);
        const bool more = (c < NCHUNK - 1);
        if (more) copyW(c + 1, cur ^ 1);
        mma_ks(0, xb, wb);
        if (more && group == 0) buildX_part(c + 1, cur ^ 1, 0);
        mma_ks(1, xb, wb);
        mma_ks(2, xb, wb);
        if (more && group == 1) buildX_part(c + 1, cur ^ 1, 32);
        mma_ks(3, xb, wb);
        if (more) {
            cp_wait_all();
            __syncthreads();
        }
    }

    // ---- epilogue: +bs-tail +bmid, tanh, dot Wout, reduce over N ----
    const int g = lane >> 2;
    float bsv[2][2][4];
#pragma unroll
    for (int t = 0; t < 2; t++)
#pragma unroll
        for (int h = 0; h < 2; h++) {
            const int row = mwarp + t * 16 + g + h * 8;
            const float* bsp = bscore
                + ((b * L_ + p0 + (row >> 4)) * NC_) * L_ + a0 + (row & 15);
#pragma unroll
            for (int ct = 0; ct < 4; ct++) bsv[t][h][ct] = bsp[ct * L_];
        }

    float part[2][2] = {{0.0f, 0.0f}, {0.0f, 0.0f}};
#pragma unroll
    for (int q2 = 0; q2 < 8; q2++) {
        const int j0 = nwarp + q2 * 8 + (lane & 3) * 2;
        const float bm0 = bmid_s[j0], bm1 = bmid_s[j0 + 1];
        const float wo0 = wout_s[j0], wo1 = wout_s[j0 + 1];
        float wt0[4], wt1[4];
#pragma unroll
        for (int ct = 0; ct < 4; ct++) {
            wt0[ct] = wtail_s[ct * 256 + j0];
            wt1[ct] = wtail_s[ct * 256 + j0 + 1];
        }
#pragma unroll
        for (int t = 0; t < 2; t++)
#pragma unroll
            for (int h = 0; h < 2; h++) {
                float v0 = acc[t][q2][h * 2 + 0] + bm0;
                float v1 = acc[t][q2][h * 2 + 1] + bm1;
#pragma unroll
                for (int ct = 0; ct < 4; ct++) {
                    v0 = fmaf(bsv[t][h][ct], wt0[ct], v0);
                    v1 = fmaf(bsv[t][h][ct], wt1[ct], v1);
                }
                part[t][h] = fmaf(fast_tanh(v0), wo0, part[t][h]);
                part[t][h] = fmaf(fast_tanh(v1), wo1, part[t][h]);
            }
    }
#pragma unroll
    for (int t = 0; t < 2; t++)
#pragma unroll
        for (int h = 0; h < 2; h++) {
            float v = part[t][h];
            v += __shfl_xor_sync(0xFFFFFFFFu, v, 1, 4);
            v += __shfl_xor_sync(0xFFFFFFFFu, v, 2, 4);
            if ((lane & 3) == 0) {
                const int row = mwarp + t * 16 + g + h * 8;
                part_s[row * 4 + (wid >> 2)] = v;
            }
        }
    __syncthreads();

    if (tid < 128) {
        const float s = part_s[tid * 4] + part_s[tid * 4 + 1]
                      + part_s[tid * 4 + 2] + part_s[tid * 4 + 3];
        const int p = p0 + (tid >> 4);
        const int a = a0 + (tid & 15);
        out[((b * L_ + p) * NC_ + n) * L_ + a] = s;
    }
}

// ---------------------------------------------------------------------------
// Launch
// ---------------------------------------------------------------------------
extern "C" void kernel_launch(void* const* d_in, const int* in_sizes, int n_in,
                              void* d_out, int out_size) {
    const float* seq    = (const float*)d_in[0];
    const float* bscore = (const float*)d_in[1];
    const float* Wp     = (const float*)d_in[2];
    const float* bp     = (const float*)d_in[3];
    const float* Wa     = (const float*)d_in[4];
    const float* ba     = (const float*)d_in[5];
    const float* Wmid   = (const float*)d_in[6];
    const float* bmid   = (const float*)d_in[7];
    const float* Wout   = (const float*)d_in[8];
    float* out = (float*)d_out;

    prep_kernel<<<PREP_BLOCKS, 256>>>(seq, Wp, bp, Wa, ba, Wmid);

    cudaFuncSetAttribute(refine_kernel,
                         cudaFuncAttributeMaxDynamicSharedMemorySize, SMEM_BYTES);
    refine_kernel<<<dim3(L_ / 16, L_ / 8, B_ * NC_), NTHR, SMEM_BYTES>>>(
        bscore, Wmid, bmid, Wout, out);
}

// round 9
// speedup vs baseline: 1.1653x; 1.0912x over previous
#include <cuda_runtime.h>
#include <cuda_bf16.h>
#include <cstdint>

// Problem constants (fixed by the dataset)
#define B_  2
#define L_  192
#define D_  768
#define NC_ 4
#define H_  256

#define KCH     64              // k per chunk in refine
#define NCHUNK  4               // K = 256 = 4 x 64 (bs tail folded into epilogue)
#define NTHR    512             // refine threads (16 warps)
#define ROWB    144             // padded row stride: 64 bf16 = 128B + 16B pad

#define WIMG_BYTES (256 * ROWB) // one W half-image: 256 n-rows x 144B

// Refine SMEM layout (byte offsets into dynamic smem)
#define OXB(buf)  ((buf) * 36864)            // X buf: XH at +0, XL at +18432
#define OWB(buf)  (73728 + (buf) * 73728)    // W buf: WH at +0, WL at +36864
#define OBMID     221184
#define OWOUT     222208
#define OWTAIL    223232                      // float[4][256]
#define OPART     227328                      // float[128][4]
#define SMEM_BYTES 229376

#define PROJ_BLOCKS 120   // 6 m-tiles x 20 n-tiles
#define PREP_BLOCKS (PROJ_BLOCKS + 32)

// Scratch (no cudaMalloc allowed)
__device__ float g_hp[B_ * L_ * H_];                 // [B*L, H]
__device__ float g_ha[B_ * L_ * NC_ * H_];           // [B*L, NC*H]
__device__ __align__(16) char g_w_img[NC_ * NCHUNK * 2 * WIMG_BYTES];

// ---------------------------------------------------------------------------
// Helpers
// ---------------------------------------------------------------------------
// Hardware tanh: single MUFU.TANH op (sm_75+ baseline PTX).
__device__ __forceinline__ float htanh(float x) {
    float y;
    asm("tanh.approx.f32 %0, %1;" : "=f"(y) : "f"(x));
    return y;
}

__device__ __forceinline__ uint32_t bf16pack(float a, float b) {
    uint32_t r;
    asm("cvt.rn.bf16x2.f32 %0, %1, %2;" : "=r"(r) : "f"(b), "f"(a));
    return r;
}
__device__ __forceinline__ float bf_lo(uint32_t u) { return __uint_as_float(u << 16); }
__device__ __forceinline__ float bf_hi(uint32_t u) { return __uint_as_float(u & 0xFFFF0000u); }

__device__ __forceinline__ unsigned long long pack2(float x) {
    unsigned long long r;
    asm("mov.b64 %0, {%1, %1};" : "=l"(r) : "f"(x));
    return r;
}
__device__ __forceinline__ unsigned long long ffma2(unsigned long long a,
                                                    unsigned long long b,
                                                    unsigned long long c) {
    unsigned long long d;
    asm("fma.rn.f32x2 %0, %1, %2, %3;" : "=l"(d) : "l"(a), "l"(b), "l"(c));
    return d;
}
__device__ __forceinline__ void unpack2(unsigned long long v, float& lo, float& hi) {
    asm("mov.b64 {%0, %1}, %2;" : "=f"(lo), "=f"(hi) : "l"(v));
}

__device__ __forceinline__ void cp_async16(uint32_t smem, const void* gptr) {
    asm volatile("cp.async.cg.shared.global [%0], [%1], 16;" :: "r"(smem), "l"(gptr));
}
__device__ __forceinline__ void cp_commit() { asm volatile("cp.async.commit_group;"); }
__device__ __forceinline__ void cp_wait_all() { asm volatile("cp.async.wait_group 0;" ::: "memory"); }

__device__ __forceinline__ void sts128(uint32_t addr, uint32_t r0, uint32_t r1,
                                       uint32_t r2, uint32_t r3) {
    asm volatile("st.shared.v4.b32 [%0], {%1, %2, %3, %4};"
                 :: "r"(addr), "r"(r0), "r"(r1), "r"(r2), "r"(r3) : "memory");
}

__device__ __forceinline__ void ldsm4(uint32_t* r, uint32_t addr) {
    asm volatile("ldmatrix.sync.aligned.m8n8.x4.shared.b16 {%0,%1,%2,%3}, [%4];"
                 : "=r"(r[0]), "=r"(r[1]), "=r"(r[2]), "=r"(r[3]) : "r"(addr));
}

__device__ __forceinline__ void mma16816(float* d, const uint32_t* a, const uint32_t* b) {
    asm volatile("mma.sync.aligned.m16n8k16.row.col.f32.bf16.bf16.f32 "
                 "{%0,%1,%2,%3}, {%4,%5,%6,%7}, {%8,%9}, {%0,%1,%2,%3};"
                 : "+f"(d[0]), "+f"(d[1]), "+f"(d[2]), "+f"(d[3])
                 : "r"(a[0]), "r"(a[1]), "r"(a[2]), "r"(a[3]),
                   "r"(b[0]), "r"(b[1]));
}

// ---------------------------------------------------------------------------
// Kernel 1 (fused): proj (blocks 0..119) + wsplit (blocks 120..151)
// ---------------------------------------------------------------------------
__global__ __launch_bounds__(256) void prep_kernel(
    const float* __restrict__ seq,
    const float* __restrict__ Wp, const float* __restrict__ bp,
    const float* __restrict__ Wa, const float* __restrict__ ba,
    const float* __restrict__ Wmid)
{
    const int tid = threadIdx.x;
    const int bx = blockIdx.x;

    if (bx >= PROJ_BLOCKS) {
        // ---- wsplit: 32 blocks, each n x chunk x half-of-kp ----
        const int idx = bx - PROJ_BLOCKS;
        const int n = idx >> 3, c = (idx >> 1) & 3, half = idx & 1;
        const int j = tid;
        char* imgH = g_w_img + (size_t)((n * NCHUNK + c) * 2) * WIMG_BYTES;
        char* imgL = imgH + WIMG_BYTES;
#pragma unroll 1
        for (int kp = half * 16; kp < half * 16 + 16; kp++) {
            const int k0 = c * KCH + kp * 2;
            const float w0 = Wmid[(n * (H_ + NC_) + k0    ) * H_ + j];
            const float w1 = Wmid[(n * (H_ + NC_) + k0 + 1) * H_ + j];
            const uint32_t h = bf16pack(w0, w1);
            const uint32_t l = bf16pack(w0 - bf_lo(h), w1 - bf_hi(h));
            *(uint32_t*)(imgH + j * ROWB + kp * 4) = h;
            *(uint32_t*)(imgL + j * ROWB + kp * 4) = l;
        }
        if (half == 0) {
            *(uint4*)(imgH + j * ROWB + 128) = make_uint4(0, 0, 0, 0);
            *(uint4*)(imgL + j * ROWB + 128) = make_uint4(0, 0, 0, 0);
        }
        return;
    }

    // ---- proj: tile 64x64, KC=32, double-buffered ----
    __shared__ __align__(16) float As[2][32][68];   // [buf][k][m] padded
    __shared__ __align__(16) float Bs[2][32][64];   // [buf][k][n]

    const int tx = tid & 15;
    const int ty = tid >> 4;
    const int m0 = (bx / 20) * 64;
    const int n0 = (bx % 20) * 64;

    const float* Wsrc;
    int ld, coff;
    if (n0 < H_) { Wsrc = Wp; ld = H_;        coff = n0; }
    else         { Wsrc = Wa; ld = NC_ * H_;  coff = n0 - H_; }

    const int lm = tid >> 3;
    const int lk = (tid & 7) * 4;

    auto copyB = [&](int kc, int buf) {
        const uint32_t dst = (uint32_t)__cvta_generic_to_shared(&Bs[buf][0][0]);
#pragma unroll
        for (int i = 0; i < 2; i++) {
            const int e = i * 256 + tid;
            const int row = e >> 4, c4 = e & 15;
            cp_async16(dst + (uint32_t)(row * 256 + c4 * 16),
                       Wsrc + (size_t)(kc + row) * ld + coff + c4 * 4);
        }
        cp_commit();
    };
    auto ldgA = [&](int kc, float4* a) {
        a[0] = *(const float4*)(seq + (size_t)(m0 + lm) * D_ + kc + lk);
        a[1] = *(const float4*)(seq + (size_t)(m0 + lm + 32) * D_ + kc + lk);
    };
    auto stsA = [&](const float4* a, int buf) {
#pragma unroll
        for (int j = 0; j < 4; j++) {
            As[buf][lk + j][lm] = ((const float*)&a[0])[j];
            As[buf][lk + j][lm + 32] = ((const float*)&a[1])[j];
        }
    };

    unsigned long long acc2[4][2];
#pragma unroll
    for (int i = 0; i < 4; i++) { acc2[i][0] = 0ull; acc2[i][1] = 0ull; }

    float4 areg[2];
    copyB(0, 0);
    ldgA(0, areg);
    stsA(areg, 0);
    cp_wait_all();
    __syncthreads();

#pragma unroll 1
    for (int c = 0; c < 24; c++) {
        const int buf = c & 1;
        if (c < 23) {
            copyB((c + 1) * 32, buf ^ 1);
            ldgA((c + 1) * 32, areg);
        }
#pragma unroll
        for (int k = 0; k < 32; k++) {
            const float4 a4 = *(const float4*)&As[buf][k][ty * 4];
            const ulonglong2 b2 = *(const ulonglong2*)&Bs[buf][k][tx * 4];
            const unsigned long long pa[4] = {pack2(a4.x), pack2(a4.y),
                                              pack2(a4.z), pack2(a4.w)};
#pragma unroll
            for (int i = 0; i < 4; i++) {
                acc2[i][0] = ffma2(pa[i], b2.x, acc2[i][0]);
                acc2[i][1] = ffma2(pa[i], b2.y, acc2[i][1]);
            }
        }
        if (c < 23) {
            stsA(areg, buf ^ 1);
            cp_wait_all();
            __syncthreads();
        }
    }

#pragma unroll
    for (int i = 0; i < 4; i++) {
        const int r = m0 + ty * 4 + i;
#pragma unroll
        for (int j = 0; j < 2; j++) {
            float lo, hi;
            unpack2(acc2[i][j], lo, hi);
            const int cg = n0 + tx * 4 + j * 2;
            if (cg < H_) {
                g_hp[r * H_ + cg] = lo + bp[cg];
                g_hp[r * H_ + cg + 1] = hi + bp[cg + 1];
            } else {
                const int c2 = cg - H_;
                g_ha[r * (NC_ * H_) + c2] = lo + ba[c2];
                g_ha[r * (NC_ * H_) + c2 + 1] = hi + ba[c2 + 1];
            }
        }
    }
}

// ---------------------------------------------------------------------------
// Kernel 2: refinement via mma.sync m16n8k16 bf16 (split hi/lo, 3 terms).
// Block (b, n, 8p x 16a): D[128,256] = X[128,256] @ W[256,256] + bs-tail (epi).
// 512 threads = 16 warps, 4(M)x4(N), warp tile 32x64.
// 4-way producer staggering: group g = wid>>2 (one warp per SMSP) builds
// k-quarter g of chunk c+1 after mma k-step g, so 3 of 4 warps per SMSP
// always issue MMAs.
// ---------------------------------------------------------------------------
__global__ __launch_bounds__(NTHR, 1) void refine_kernel(
    const float* __restrict__ bscore,   // [B, L, NC, L]
    const float* __restrict__ Wmid,     // [NC, H+NC, H]
    const float* __restrict__ bmid,     // [NC, H]
    const float* __restrict__ Wout,     // [NC, H]
    float* __restrict__ out)            // [B, L, NC, L]
{
    extern __shared__ __align__(16) char sm[];
    const uint32_t base = (uint32_t)__cvta_generic_to_shared(sm);

    float* bmid_s  = (float*)(sm + OBMID);
    float* wout_s  = (float*)(sm + OWOUT);
    float* wtail_s = (float*)(sm + OWTAIL);  // [4][256]
    float* part_s  = (float*)(sm + OPART);   // [128][4]

    const int tid = threadIdx.x;
    const int wid = tid >> 5;
    const int lane = tid & 31;
    const int bz = blockIdx.z;
    const int b = bz >> 2, n = bz & 3;
    const int p0 = blockIdx.y * 8;
    const int a0 = blockIdx.x * 16;

    const int mwarp = (wid & 3) * 32;
    const int nwarp = (wid >> 2) * 64;

    // producer group: wid>>2 -> warps {4g..4g+3} = one per SMSP
    const int group = wid >> 2;
    const int gl = (wid & 3) * 32 + lane;    // 0..127 within group

    // epilogue tables
    if (tid < 256) {
        bmid_s[tid] = bmid[n * H_ + tid];
        wout_s[tid] = Wout[n * H_ + tid];
    }
#pragma unroll
    for (int q = 0; q < 2; q++) {
        const int i = q * NTHR + tid;
        wtail_s[i] = Wmid[(n * (H_ + NC_) + H_ + (i >> 8)) * H_ + (i & 255)];
    }

    // build mapping: thread = one m-row (gl), 16 consecutive k per build call
    const int bm = gl;
    const int bp_ = p0 + (bm >> 4);
    const int ba_ = a0 + (bm & 15);
    const float* hp_row = g_hp + (b * L_ + bp_) * H_;
    const float* ha_row = g_ha + ((b * L_ + ba_) * NC_ + n) * H_;

    // lane-constant ldmatrix address offsets
    const uint32_t a_off = (uint32_t)((mwarp + (lane & 15)) * ROWB + ((lane >> 4) << 4));
    const uint32_t b_off = (uint32_t)((nwarp + (lane & 7) + ((lane & 16) ? 8 : 0)) * ROWB
                                      + ((lane & 8) ? 16 : 0));

    // build 16 k-values of chunk c at k-offset qoff (row bm) into buffer buf
    auto buildX_part = [&](int c, int buf, int qoff) {
        const uint32_t xh = base + OXB(buf) + (uint32_t)(bm * ROWB + qoff * 2);
        const uint32_t xl = xh + 18432;
        const float4* hp4 = (const float4*)(hp_row + c * KCH + qoff);
        const float4* ha4 = (const float4*)(ha_row + c * KCH + qoff);
        uint32_t hw[8], lw[8];
#pragma unroll
        for (int g = 0; g < 4; g++) {
            const float4 u = hp4[g];
            const float4 v = ha4[g];
            const float x0 = htanh(u.x + v.x);
            const float x1 = htanh(u.y + v.y);
            const float x2 = htanh(u.z + v.z);
            const float x3 = htanh(u.w + v.w);
            const uint32_t hA = bf16pack(x0, x1);
            const uint32_t hB = bf16pack(x2, x3);
            hw[g * 2 + 0] = hA;
            hw[g * 2 + 1] = hB;
            lw[g * 2 + 0] = bf16pack(x0 - bf_lo(hA), x1 - bf_hi(hA));
            lw[g * 2 + 1] = bf16pack(x2 - bf_lo(hB), x3 - bf_hi(hB));
        }
        sts128(xh,      hw[0], hw[1], hw[2], hw[3]);
        sts128(xh + 16, hw[4], hw[5], hw[6], hw[7]);
        sts128(xl,      lw[0], lw[1], lw[2], lw[3]);
        sts128(xl + 16, lw[4], lw[5], lw[6], lw[7]);
    };

    auto copyW = [&](int c, int buf) {
        const char* src = g_w_img + (size_t)((n * NCHUNK + c) * 2) * WIMG_BYTES;
        const uint32_t dst = base + OWB(buf);
#pragma unroll
        for (int i = 0; i < 9; i++) {
            const int e = i * NTHR + tid;
            cp_async16(dst + e * 16, src + (size_t)e * 16);
        }
        cp_commit();
    };

    float acc[2][8][4];
#pragma unroll
    for (int t = 0; t < 2; t++)
#pragma unroll
        for (int q = 0; q < 8; q++)
#pragma unroll
            for (int r = 0; r < 4; r++) acc[t][q][r] = 0.0f;

    // one k16-step: shared fragments across the 3 split terms
    auto mma_ks = [&](int ks, uint32_t xb, uint32_t wb) {
        uint32_t AH0[4], AH1[4], AL0[4], AL1[4], Bf[4][4];
        const uint32_t kb = (uint32_t)(ks * 32);
        ldsm4(AH0, xb + a_off + kb);
        ldsm4(AH1, xb + a_off + 16 * ROWB + kb);
        ldsm4(AL0, xb + 18432 + a_off + kb);
        ldsm4(AL1, xb + 18432 + a_off + 16 * ROWB + kb);
#pragma unroll
        for (int q = 0; q < 4; q++)
            ldsm4(Bf[q], wb + b_off + q * 16 * ROWB + kb);
        // seg0 (XH*WH) + seg1 (XL*WH)
#pragma unroll
        for (int q2 = 0; q2 < 8; q2++) {
            const uint32_t* bq = &Bf[q2 >> 1][(q2 & 1) * 2];
            mma16816(acc[0][q2], AH0, bq);
            mma16816(acc[1][q2], AH1, bq);
            mma16816(acc[0][q2], AL0, bq);
            mma16816(acc[1][q2], AL1, bq);
        }
        // seg2 (XH*WL)
#pragma unroll
        for (int q = 0; q < 4; q++)
            ldsm4(Bf[q], wb + 36864 + b_off + q * 16 * ROWB + kb);
#pragma unroll
        for (int q2 = 0; q2 < 8; q2++) {
            const uint32_t* bq = &Bf[q2 >> 1][(q2 & 1) * 2];
            mma16816(acc[0][q2], AH0, bq);
            mma16816(acc[1][q2], AH1, bq);
        }
    };

    // ---- prologue: each group builds its quarter of chunk 0 ----
    copyW(0, 0);
    buildX_part(0, 0, group * 16);
    cp_wait_all();
    __syncthreads();

#pragma unroll 1
    for (int c = 0; c < NCHUNK; c++) {
        const int cur = c & 1;
        const uint32_t xb = base + OXB(cur);
        const uint32_t wb = base + OWB(cur);
        const bool more = (c < NCHUNK - 1);
        if (more) copyW(c + 1, cur ^ 1);
        mma_ks(0, xb, wb);
        if (more && group == 0) buildX_part(c + 1, cur ^ 1, 0);
        mma_ks(1, xb, wb);
        if (more && group == 1) buildX_part(c + 1, cur ^ 1, 16);
        mma_ks(2, xb, wb);
        if (more && group == 2) buildX_part(c + 1, cur ^ 1, 32);
        mma_ks(3, xb, wb);
        if (more && group == 3) buildX_part(c + 1, cur ^ 1, 48);
        if (more) {
            cp_wait_all();
            __syncthreads();
        }
    }

    // ---- epilogue: +bs-tail +bmid, tanh, dot Wout, reduce over N ----
    const int g = lane >> 2;
    float bsv[2][2][4];
#pragma unroll
    for (int t = 0; t < 2; t++)
#pragma unroll
        for (int h = 0; h < 2; h++) {
            const int row = mwarp + t * 16 + g + h * 8;
            const float* bsp = bscore
                + ((b * L_ + p0 + (row >> 4)) * NC_) * L_ + a0 + (row & 15);
#pragma unroll
            for (int ct = 0; ct < 4; ct++) bsv[t][h][ct] = bsp[ct * L_];
        }

    float part[2][2] = {{0.0f, 0.0f}, {0.0f, 0.0f}};
#pragma unroll
    for (int q2 = 0; q2 < 8; q2++) {
        const int j0 = nwarp + q2 * 8 + (lane & 3) * 2;
        const float bm0 = bmid_s[j0], bm1 = bmid_s[j0 + 1];
        const float wo0 = wout_s[j0], wo1 = wout_s[j0 + 1];
        float wt0[4], wt1[4];
#pragma unroll
        for (int ct = 0; ct < 4; ct++) {
            wt0[ct] = wtail_s[ct * 256 + j0];
            wt1[ct] = wtail_s[ct * 256 + j0 + 1];
        }
#pragma unroll
        for (int t = 0; t < 2; t++)
#pragma unroll
            for (int h = 0; h < 2; h++) {
                float v0 = acc[t][q2][h * 2 + 0] + bm0;
                float v1 = acc[t][q2][h * 2 + 1] + bm1;
#pragma unroll
                for (int ct = 0; ct < 4; ct++) {
                    v0 = fmaf(bsv[t][h][ct], wt0[ct], v0);
                    v1 = fmaf(bsv[t][h][ct], wt1[ct], v1);
                }
                part[t][h] = fmaf(htanh(v0), wo0, part[t][h]);
                part[t][h] = fmaf(htanh(v1), wo1, part[t][h]);
            }
    }
#pragma unroll
    for (int t = 0; t < 2; t++)
#pragma unroll
        for (int h = 0; h < 2; h++) {
            float v = part[t][h];
            v += __shfl_xor_sync(0xFFFFFFFFu, v, 1, 4);
            v += __shfl_xor_sync(0xFFFFFFFFu, v, 2, 4);
            if ((lane & 3) == 0) {
                const int row = mwarp + t * 16 + g + h * 8;
                part_s[row * 4 + (wid >> 2)] = v;
            }
        }
    __syncthreads();

    if (tid < 128) {
        const float s = part_s[tid * 4] + part_s[tid * 4 + 1]
                      + part_s[tid * 4 + 2] + part_s[tid * 4 + 3];
        const int p = p0 + (tid >> 4);
        const int a = a0 + (tid & 15);
        out[((b * L_ + p) * NC_ + n) * L_ + a] = s;
    }
}

// ---------------------------------------------------------------------------
// Launch
// ---------------------------------------------------------------------------
extern "C" void kernel_launch(void* const* d_in, const int* in_sizes, int n_in,
                              void* d_out, int out_size) {
    const float* seq    = (const float*)d_in[0];
    const float* bscore = (const float*)d_in[1];
    const float* Wp     = (const float*)d_in[2];
    const float* bp     = (const float*)d_in[3];
    const float* Wa     = (const float*)d_in[4];
    const float* ba     = (const float*)d_in[5];
    const float* Wmid   = (const float*)d_in[6];
    const float* bmid   = (const float*)d_in[7];
    const float* Wout   = (const float*)d_in[8];
    float* out = (float*)d_out;

    prep_kernel<<<PREP_BLOCKS, 256>>>(seq, Wp, bp, Wa, ba, Wmid);

    cudaFuncSetAttribute(refine_kernel,
                         cudaFuncAttributeMaxDynamicSharedMemorySize, SMEM_BYTES);
    refine_kernel<<<dim3(L_ / 16, L_ / 8, B_ * NC_), NTHR, SMEM_BYTES>>>(
        bscore, Wmid, bmid, Wout, out);
}

// round 10
// speedup vs baseline: 1.1840x; 1.0160x over previous
#include <cuda_runtime.h>
#include <cuda_bf16.h>
#include <cstdint>

// Problem constants (fixed by the dataset)
#define B_  2
#define L_  192
#define D_  768
#define NC_ 4
#define H_  256

#define KCH     64              // k per chunk in refine
#define NCHUNK  4               // K = 256 = 4 x 64 (bs tail folded into epilogue)
#define NTHR    512             // refine threads (16 warps)
#define ROWB    144             // padded row stride: 64 bf16 = 128B + 16B pad

#define WIMG_BYTES (256 * ROWB) // one W half-image: 256 n-rows x 144B

// Refine SMEM layout (byte offsets into dynamic smem)
#define OXB(buf)  ((buf) * 36864)            // X buf: XH at +0, XL at +18432
#define OWB(buf)  (73728 + (buf) * 73728)    // W buf: WH at +0, WL at +36864
#define OBMID     221184
#define OWOUT     222208
#define OWTAIL    223232                      // float[4][256]
#define OPART     227328                      // float[128][4]
#define SMEM_BYTES 229376

#define PROJ_BLOCKS 120   // 6 m-tiles x 20 n-tiles
#define PREP_BLOCKS (PROJ_BLOCKS + 32)

// Scratch (no cudaMalloc allowed)
__device__ float g_hp[B_ * L_ * H_];                 // [B*L, H]
__device__ float g_ha[B_ * L_ * NC_ * H_];           // [B*L, NC*H]
__device__ __align__(16) char g_w_img[NC_ * NCHUNK * 2 * WIMG_BYTES];

// ---------------------------------------------------------------------------
// Helpers
// ---------------------------------------------------------------------------
// Hardware tanh: single MUFU.TANH op (sm_75+ baseline PTX).
__device__ __forceinline__ float htanh(float x) {
    float y;
    asm("tanh.approx.f32 %0, %1;" : "=f"(y) : "f"(x));
    return y;
}

__device__ __forceinline__ uint32_t bf16pack(float a, float b) {
    uint32_t r;
    asm("cvt.rn.bf16x2.f32 %0, %1, %2;" : "=r"(r) : "f"(b), "f"(a));
    return r;
}
__device__ __forceinline__ float bf_lo(uint32_t u) { return __uint_as_float(u << 16); }
__device__ __forceinline__ float bf_hi(uint32_t u) { return __uint_as_float(u & 0xFFFF0000u); }

__device__ __forceinline__ unsigned long long pack2(float x) {
    unsigned long long r;
    asm("mov.b64 %0, {%1, %1};" : "=l"(r) : "f"(x));
    return r;
}
__device__ __forceinline__ unsigned long long ffma2(unsigned long long a,
                                                    unsigned long long b,
                                                    unsigned long long c) {
    unsigned long long d;
    asm("fma.rn.f32x2 %0, %1, %2, %3;" : "=l"(d) : "l"(a), "l"(b), "l"(c));
    return d;
}
__device__ __forceinline__ void unpack2(unsigned long long v, float& lo, float& hi) {
    asm("mov.b64 {%0, %1}, %2;" : "=f"(lo), "=f"(hi) : "l"(v));
}

__device__ __forceinline__ void cp_async16(uint32_t smem, const void* gptr) {
    asm volatile("cp.async.cg.shared.global [%0], [%1], 16;" :: "r"(smem), "l"(gptr));
}
__device__ __forceinline__ void cp_commit() { asm volatile("cp.async.commit_group;"); }
__device__ __forceinline__ void cp_wait_all() { asm volatile("cp.async.wait_group 0;" ::: "memory"); }

__device__ __forceinline__ void sts128(uint32_t addr, uint32_t r0, uint32_t r1,
                                       uint32_t r2, uint32_t r3) {
    asm volatile("st.shared.v4.b32 [%0], {%1, %2, %3, %4};"
                 :: "r"(addr), "r"(r0), "r"(r1), "r"(r2), "r"(r3) : "memory");
}

__device__ __forceinline__ void ldsm4(uint32_t* r, uint32_t addr) {
    asm volatile("ldmatrix.sync.aligned.m8n8.x4.shared.b16 {%0,%1,%2,%3}, [%4];"
                 : "=r"(r[0]), "=r"(r[1]), "=r"(r[2]), "=r"(r[3]) : "r"(addr));
}

__device__ __forceinline__ void mma16816(float* d, const uint32_t* a, const uint32_t* b) {
    asm volatile("mma.sync.aligned.m16n8k16.row.col.f32.bf16.bf16.f32 "
                 "{%0,%1,%2,%3}, {%4,%5,%6,%7}, {%8,%9}, {%0,%1,%2,%3};"
                 : "+f"(d[0]), "+f"(d[1]), "+f"(d[2]), "+f"(d[3])
                 : "r"(a[0]), "r"(a[1]), "r"(a[2]), "r"(a[3]),
                   "r"(b[0]), "r"(b[1]));
}

// ---------------------------------------------------------------------------
// Kernel 1 (fused): proj (blocks 0..119) + wsplit (blocks 120..151)
// ---------------------------------------------------------------------------
__global__ __launch_bounds__(256) void prep_kernel(
    const float* __restrict__ seq,
    const float* __restrict__ Wp, const float* __restrict__ bp,
    const float* __restrict__ Wa, const float* __restrict__ ba,
    const float* __restrict__ Wmid)
{
    const int tid = threadIdx.x;
    const int bx = blockIdx.x;

    if (bx >= PROJ_BLOCKS) {
        // ---- wsplit: 32 blocks, each n x chunk x half-of-kp ----
        const int idx = bx - PROJ_BLOCKS;
        const int n = idx >> 3, c = (idx >> 1) & 3, half = idx & 1;
        const int j = tid;
        char* imgH = g_w_img + (size_t)((n * NCHUNK + c) * 2) * WIMG_BYTES;
        char* imgL = imgH + WIMG_BYTES;
#pragma unroll 1
        for (int kp = half * 16; kp < half * 16 + 16; kp++) {
            const int k0 = c * KCH + kp * 2;
            const float w0 = Wmid[(n * (H_ + NC_) + k0    ) * H_ + j];
            const float w1 = Wmid[(n * (H_ + NC_) + k0 + 1) * H_ + j];
            const uint32_t h = bf16pack(w0, w1);
            const uint32_t l = bf16pack(w0 - bf_lo(h), w1 - bf_hi(h));
            *(uint32_t*)(imgH + j * ROWB + kp * 4) = h;
            *(uint32_t*)(imgL + j * ROWB + kp * 4) = l;
        }
        if (half == 0) {
            *(uint4*)(imgH + j * ROWB + 128) = make_uint4(0, 0, 0, 0);
            *(uint4*)(imgL + j * ROWB + 128) = make_uint4(0, 0, 0, 0);
        }
        return;
    }

    // ---- proj: tile 64x64, KC=32, double-buffered ----
    __shared__ __align__(16) float As[2][32][68];   // [buf][k][m] padded
    __shared__ __align__(16) float Bs[2][32][64];   // [buf][k][n]

    const int tx = tid & 15;
    const int ty = tid >> 4;
    const int m0 = (bx / 20) * 64;
    const int n0 = (bx % 20) * 64;

    const float* Wsrc;
    int ld, coff;
    if (n0 < H_) { Wsrc = Wp; ld = H_;        coff = n0; }
    else         { Wsrc = Wa; ld = NC_ * H_;  coff = n0 - H_; }

    const int lm = tid >> 3;
    const int lk = (tid & 7) * 4;

    auto copyB = [&](int kc, int buf) {
        const uint32_t dst = (uint32_t)__cvta_generic_to_shared(&Bs[buf][0][0]);
#pragma unroll
        for (int i = 0; i < 2; i++) {
            const int e = i * 256 + tid;
            const int row = e >> 4, c4 = e & 15;
            cp_async16(dst + (uint32_t)(row * 256 + c4 * 16),
                       Wsrc + (size_t)(kc + row) * ld + coff + c4 * 4);
        }
        cp_commit();
    };
    auto ldgA = [&](int kc, float4* a) {
        a[0] = *(const float4*)(seq + (size_t)(m0 + lm) * D_ + kc + lk);
        a[1] = *(const float4*)(seq + (size_t)(m0 + lm + 32) * D_ + kc + lk);
    };
    auto stsA = [&](const float4* a, int buf) {
#pragma unroll
        for (int j = 0; j < 4; j++) {
            As[buf][lk + j][lm] = ((const float*)&a[0])[j];
            As[buf][lk + j][lm + 32] = ((const float*)&a[1])[j];
        }
    };

    unsigned long long acc2[4][2];
#pragma unroll
    for (int i = 0; i < 4; i++) { acc2[i][0] = 0ull; acc2[i][1] = 0ull; }

    float4 areg[2];
    copyB(0, 0);
    ldgA(0, areg);
    stsA(areg, 0);
    cp_wait_all();
    __syncthreads();

#pragma unroll 1
    for (int c = 0; c < 24; c++) {
        const int buf = c & 1;
        if (c < 23) {
            copyB((c + 1) * 32, buf ^ 1);
            ldgA((c + 1) * 32, areg);
        }
#pragma unroll
        for (int k = 0; k < 32; k++) {
            const float4 a4 = *(const float4*)&As[buf][k][ty * 4];
            const ulonglong2 b2 = *(const ulonglong2*)&Bs[buf][k][tx * 4];
            const unsigned long long pa[4] = {pack2(a4.x), pack2(a4.y),
                                              pack2(a4.z), pack2(a4.w)};
#pragma unroll
            for (int i = 0; i < 4; i++) {
                acc2[i][0] = ffma2(pa[i], b2.x, acc2[i][0]);
                acc2[i][1] = ffma2(pa[i], b2.y, acc2[i][1]);
            }
        }
        if (c < 23) {
            stsA(areg, buf ^ 1);
            cp_wait_all();
            __syncthreads();
        }
    }

#pragma unroll
    for (int i = 0; i < 4; i++) {
        const int r = m0 + ty * 4 + i;
#pragma unroll
        for (int j = 0; j < 2; j++) {
            float lo, hi;
            unpack2(acc2[i][j], lo, hi);
            const int cg = n0 + tx * 4 + j * 2;
            if (cg < H_) {
                g_hp[r * H_ + cg] = lo + bp[cg];
                g_hp[r * H_ + cg + 1] = hi + bp[cg + 1];
            } else {
                const int c2 = cg - H_;
                g_ha[r * (NC_ * H_) + c2] = lo + ba[c2];
                g_ha[r * (NC_ * H_) + c2 + 1] = hi + ba[c2 + 1];
            }
        }
    }
}

// ---------------------------------------------------------------------------
// Kernel 2: refinement via mma.sync m16n8k16 bf16 (split hi/lo, 3 terms).
// Block (b, n, 8p x 16a): D[128,256] = X[128,256] @ W[256,256] + bs-tail (epi).
// 512 threads = 16 warps, 4(M)x4(N), warp tile 32x64.
// MMA ordering: 3 passes of 16 independent MMAs -> accumulator reuse
// distance = 16 (was 2). 4-way producer staggering, no exposed tail build.
// ---------------------------------------------------------------------------
__global__ __launch_bounds__(NTHR, 1) void refine_kernel(
    const float* __restrict__ bscore,   // [B, L, NC, L]
    const float* __restrict__ Wmid,     // [NC, H+NC, H]
    const float* __restrict__ bmid,     // [NC, H]
    const float* __restrict__ Wout,     // [NC, H]
    float* __restrict__ out)            // [B, L, NC, L]
{
    extern __shared__ __align__(16) char sm[];
    const uint32_t base = (uint32_t)__cvta_generic_to_shared(sm);

    float* bmid_s  = (float*)(sm + OBMID);
    float* wout_s  = (float*)(sm + OWOUT);
    float* wtail_s = (float*)(sm + OWTAIL);  // [4][256]
    float* part_s  = (float*)(sm + OPART);   // [128][4]

    const int tid = threadIdx.x;
    const int wid = tid >> 5;
    const int lane = tid & 31;
    const int bz = blockIdx.z;
    const int b = bz >> 2, n = bz & 3;
    const int p0 = blockIdx.y * 8;
    const int a0 = blockIdx.x * 16;

    const int mwarp = (wid & 3) * 32;
    const int nwarp = (wid >> 2) * 64;

    // producer group: wid>>2 -> warps {4g..4g+3} = one per SMSP
    const int group = wid >> 2;
    const int gl = (wid & 3) * 32 + lane;    // 0..127 within group

    // epilogue tables
    if (tid < 256) {
        bmid_s[tid] = bmid[n * H_ + tid];
        wout_s[tid] = Wout[n * H_ + tid];
    }
#pragma unroll
    for (int q = 0; q < 2; q++) {
        const int i = q * NTHR + tid;
        wtail_s[i] = Wmid[(n * (H_ + NC_) + H_ + (i >> 8)) * H_ + (i & 255)];
    }

    // build mapping: thread = one m-row (gl), 16 consecutive k per build call
    const int bm = gl;
    const int bp_ = p0 + (bm >> 4);
    const int ba_ = a0 + (bm & 15);
    const float* hp_row = g_hp + (b * L_ + bp_) * H_;
    const float* ha_row = g_ha + ((b * L_ + ba_) * NC_ + n) * H_;

    // lane-constant ldmatrix address offsets
    const uint32_t a_off = (uint32_t)((mwarp + (lane & 15)) * ROWB + ((lane >> 4) << 4));
    const uint32_t b_off = (uint32_t)((nwarp + (lane & 7) + ((lane & 16) ? 8 : 0)) * ROWB
                                      + ((lane & 8) ? 16 : 0));

    // build 16 k-values of chunk c at k-offset qoff (row bm) into buffer buf
    auto buildX_part = [&](int c, int buf, int qoff) {
        const uint32_t xh = base + OXB(buf) + (uint32_t)(bm * ROWB + qoff * 2);
        const uint32_t xl = xh + 18432;
        const float4* hp4 = (const float4*)(hp_row + c * KCH + qoff);
        const float4* ha4 = (const float4*)(ha_row + c * KCH + qoff);
        uint32_t hw[8], lw[8];
#pragma unroll
        for (int g = 0; g < 4; g++) {
            const float4 u = hp4[g];
            const float4 v = ha4[g];
            const float x0 = htanh(u.x + v.x);
            const float x1 = htanh(u.y + v.y);
            const float x2 = htanh(u.z + v.z);
            const float x3 = htanh(u.w + v.w);
            const uint32_t hA = bf16pack(x0, x1);
            const uint32_t hB = bf16pack(x2, x3);
            hw[g * 2 + 0] = hA;
            hw[g * 2 + 1] = hB;
            lw[g * 2 + 0] = bf16pack(x0 - bf_lo(hA), x1 - bf_hi(hA));
            lw[g * 2 + 1] = bf16pack(x2 - bf_lo(hB), x3 - bf_hi(hB));
        }
        sts128(xh,      hw[0], hw[1], hw[2], hw[3]);
        sts128(xh + 16, hw[4], hw[5], hw[6], hw[7]);
        sts128(xl,      lw[0], lw[1], lw[2], lw[3]);
        sts128(xl + 16, lw[4], lw[5], lw[6], lw[7]);
    };

    auto copyW = [&](int c, int buf) {
        const char* src = g_w_img + (size_t)((n * NCHUNK + c) * 2) * WIMG_BYTES;
        const uint32_t dst = base + OWB(buf);
#pragma unroll
        for (int i = 0; i < 9; i++) {
            const int e = i * NTHR + tid;
            cp_async16(dst + e * 16, src + (size_t)e * 16);
        }
        cp_commit();
    };

    float acc[2][8][4];
#pragma unroll
    for (int t = 0; t < 2; t++)
#pragma unroll
        for (int q = 0; q < 8; q++)
#pragma unroll
            for (int r = 0; r < 4; r++) acc[t][q][r] = 0.0f;

    // one k16-step: 3 passes of 16 independent MMAs (acc reuse distance 16).
    // Pass order caps live regs: AL dies after pass 1, BH after pass 2.
    auto mma_ks = [&](int ks, uint32_t xb, uint32_t wb) {
        uint32_t AH0[4], AH1[4], AL0[4], AL1[4], BH[4][4], BL[4][4];
        const uint32_t kb = (uint32_t)(ks * 32);
        ldsm4(AH0, xb + a_off + kb);
        ldsm4(AH1, xb + a_off + 16 * ROWB + kb);
        ldsm4(AL0, xb + 18432 + a_off + kb);
        ldsm4(AL1, xb + 18432 + a_off + 16 * ROWB + kb);
#pragma unroll
        for (int q = 0; q < 4; q++)
            ldsm4(BH[q], wb + b_off + q * 16 * ROWB + kb);
        // pass 1: XL x WH
#pragma unroll
        for (int q2 = 0; q2 < 8; q2++) {
            const uint32_t* bq = &BH[q2 >> 1][(q2 & 1) * 2];
            mma16816(acc[0][q2], AL0, bq);
            mma16816(acc[1][q2], AL1, bq);
        }
        // WL loads overlap pass-2 issue
#pragma unroll
        for (int q = 0; q < 4; q++)
            ldsm4(BL[q], wb + 36864 + b_off + q * 16 * ROWB + kb);
        // pass 2: XH x WH
#pragma unroll
        for (int q2 = 0; q2 < 8; q2++) {
            const uint32_t* bq = &BH[q2 >> 1][(q2 & 1) * 2];
            mma16816(acc[0][q2], AH0, bq);
            mma16816(acc[1][q2], AH1, bq);
        }
        // pass 3: XH x WL
#pragma unroll
        for (int q2 = 0; q2 < 8; q2++) {
            const uint32_t* bq = &BL[q2 >> 1][(q2 & 1) * 2];
            mma16816(acc[0][q2], AH0, bq);
            mma16816(acc[1][q2], AH1, bq);
        }
    };

    // ---- prologue: each group builds its quarter of chunk 0 ----
    copyW(0, 0);
    buildX_part(0, 0, group * 16);
    cp_wait_all();
    __syncthreads();

#pragma unroll 1
    for (int c = 0; c < NCHUNK; c++) {
        const int cur = c & 1;
        const uint32_t xb = base + OXB(cur);
        const uint32_t wb = base + OWB(cur);
        const bool more = (c < NCHUNK - 1);
        if (more) copyW(c + 1, cur ^ 1);
        mma_ks(0, xb, wb);
        if (more && group == 0) buildX_part(c + 1, cur ^ 1, 0);
        mma_ks(1, xb, wb);
        if (more && group == 1) buildX_part(c + 1, cur ^ 1, 16);
        if (more && group == 3) buildX_part(c + 1, cur ^ 1, 48);
        mma_ks(2, xb, wb);
        if (more && group == 2) buildX_part(c + 1, cur ^ 1, 32);
        mma_ks(3, xb, wb);
        if (more) {
            cp_wait_all();
            __syncthreads();
        }
    }

    // ---- epilogue: +bs-tail +bmid, tanh, dot Wout, reduce over N ----
    const int g = lane >> 2;
    float bsv[2][2][4];
#pragma unroll
    for (int t = 0; t < 2; t++)
#pragma unroll
        for (int h = 0; h < 2; h++) {
            const int row = mwarp + t * 16 + g + h * 8;
            const float* bsp = bscore
                + ((b * L_ + p0 + (row >> 4)) * NC_) * L_ + a0 + (row & 15);
#pragma unroll
            for (int ct = 0; ct < 4; ct++) bsv[t][h][ct] = bsp[ct * L_];
        }

    float part[2][2] = {{0.0f, 0.0f}, {0.0f, 0.0f}};
#pragma unroll
    for (int q2 = 0; q2 < 8; q2++) {
        const int j0 = nwarp + q2 * 8 + (lane & 3) * 2;
        const float bm0 = bmid_s[j0], bm1 = bmid_s[j0 + 1];
        const float wo0 = wout_s[j0], wo1 = wout_s[j0 + 1];
        float wt0[4], wt1[4];
#pragma unroll
        for (int ct = 0; ct < 4; ct++) {
            wt0[ct] = wtail_s[ct * 256 + j0];
            wt1[ct] = wtail_s[ct * 256 + j0 + 1];
        }
#pragma unroll
        for (int t = 0; t < 2; t++)
#pragma unroll
            for (int h = 0; h < 2; h++) {
                float v0 = acc[t][q2][h * 2 + 0] + bm0;
                float v1 = acc[t][q2][h * 2 + 1] + bm1;
#pragma unroll
                for (int ct = 0; ct < 4; ct++) {
                    v0 = fmaf(bsv[t][h][ct], wt0[ct], v0);
                    v1 = fmaf(bsv[t][h][ct], wt1[ct], v1);
                }
                part[t][h] = fmaf(htanh(v0), wo0, part[t][h]);
                part[t][h] = fmaf(htanh(v1), wo1, part[t][h]);
            }
    }
#pragma unroll
    for (int t = 0; t < 2; t++)
#pragma unroll
        for (int h = 0; h < 2; h++) {
            float v = part[t][h];
            v += __shfl_xor_sync(0xFFFFFFFFu, v, 1, 4);
            v += __shfl_xor_sync(0xFFFFFFFFu, v, 2, 4);
            if ((lane & 3) == 0) {
                const int row = mwarp + t * 16 + g + h * 8;
                part_s[row * 4 + (wid >> 2)] = v;
            }
        }
    __syncthreads();

    if (tid < 128) {
        const float s = part_s[tid * 4] + part_s[tid * 4 + 1]
                      + part_s[tid * 4 + 2] + part_s[tid * 4 + 3];
        const int p = p0 + (tid >> 4);
        const int a = a0 + (tid & 15);
        out[((b * L_ + p) * NC_ + n) * L_ + a] = s;
    }
}

// ---------------------------------------------------------------------------
// Launch
// ---------------------------------------------------------------------------
extern "C" void kernel_launch(void* const* d_in, const int* in_sizes, int n_in,
                              void* d_out, int out_size) {
    const float* seq    = (const float*)d_in[0];
    const float* bscore = (const float*)d_in[1];
    const float* Wp     = (const float*)d_in[2];
    const float* bp     = (const float*)d_in[3];
    const float* Wa     = (const float*)d_in[4];
    const float* ba     = (const float*)d_in[5];
    const float* Wmid   = (const float*)d_in[6];
    const float* bmid   = (const float*)d_in[7];
    const float* Wout   = (const float*)d_in[8];
    float* out = (float*)d_out;

    prep_kernel<<<PREP_BLOCKS, 256>>>(seq, Wp, bp, Wa, ba, Wmid);

    cudaFuncSetAttribute(refine_kernel,
                         cudaFuncAttributeMaxDynamicSharedMemorySize, SMEM_BYTES);
    refine_kernel<<<dim3(L_ / 16, L_ / 8, B_ * NC_), NTHR, SMEM_BYTES>>>(
        bscore, Wmid, bmid, Wout, out);
}

// round 11
// speedup vs baseline: 1.4064x; 1.1878x over previous
#include <cuda_runtime.h>
#include <cuda_bf16.h>
#include <cuda_fp16.h>
#include <cstdint>

// Problem constants (fixed by the dataset)
#define B_  2
#define L_  192
#define D_  768
#define NC_ 4
#define H_  256

#define KCH     64              // k per chunk in refine
#define NCHUNK  4               // K = 256 = 4 x 64 (bs tail folded into epilogue)
#define NTHR    512             // refine threads (16 warps)
#define ROWB    144             // padded row stride: 64 fp16 = 128B + 16B pad

#define WIMG_BYTES (256 * ROWB) // one W half-image: 256 n-rows x 144B

// Refine SMEM layout (byte offsets into dynamic smem)
#define OXB(buf)  ((buf) * 18432)            // X buf (fp16, single image)
#define OWB(buf)  (36864 + (buf) * 73728)    // W buf: WH at +0, WL at +36864
#define OBMID     184320
#define OWOUT     185344
#define OWTAIL    186368                      // float[4][256]
#define OPART     190464                      // float[128][4]
#define SMEM_BYTES 192512

#define PROJ_BLOCKS 120   // 6 m-tiles x 20 n-tiles
#define PREP_BLOCKS (PROJ_BLOCKS + 32)

// Scratch (no cudaMalloc allowed)
__device__ float g_hp[B_ * L_ * H_];                 // [B*L, H]
__device__ float g_ha[B_ * L_ * NC_ * H_];           // [B*L, NC*H]
__device__ __align__(16) char g_w_img[NC_ * NCHUNK * 2 * WIMG_BYTES];

// ---------------------------------------------------------------------------
// Helpers
// ---------------------------------------------------------------------------
// Hardware tanh: single MUFU.TANH op (sm_75+ baseline PTX).
__device__ __forceinline__ float htanh(float x) {
    float y;
    asm("tanh.approx.f32 %0, %1;" : "=f"(y) : "f"(x));
    return y;
}

// pack two floats to fp16x2: LOW half = a, HIGH half = b
__device__ __forceinline__ uint32_t f16pack(float a, float b) {
    const __half2 h = __floats2half2_rn(a, b);
    return *(const uint32_t*)&h;
}
__device__ __forceinline__ float f16_lo(uint32_t u) {
    return __half2float(*(const __half*)&u);
}
__device__ __forceinline__ float f16_hi(uint32_t u) {
    const uint16_t hh = (uint16_t)(u >> 16);
    return __half2float(*(const __half*)&hh);
}

__device__ __forceinline__ unsigned long long pack2(float x) {
    unsigned long long r;
    asm("mov.b64 %0, {%1, %1};" : "=l"(r) : "f"(x));
    return r;
}
__device__ __forceinline__ unsigned long long ffma2(unsigned long long a,
                                                    unsigned long long b,
                                                    unsigned long long c) {
    unsigned long long d;
    asm("fma.rn.f32x2 %0, %1, %2, %3;" : "=l"(d) : "l"(a), "l"(b), "l"(c));
    return d;
}
__device__ __forceinline__ void unpack2(unsigned long long v, float& lo, float& hi) {
    asm("mov.b64 {%0, %1}, %2;" : "=f"(lo), "=f"(hi) : "l"(v));
}

__device__ __forceinline__ void cp_async16(uint32_t smem, const void* gptr) {
    asm volatile("cp.async.cg.shared.global [%0], [%1], 16;" :: "r"(smem), "l"(gptr));
}
__device__ __forceinline__ void cp_commit() { asm volatile("cp.async.commit_group;"); }
__device__ __forceinline__ void cp_wait_all() { asm volatile("cp.async.wait_group 0;" ::: "memory"); }

__device__ __forceinline__ void sts128(uint32_t addr, uint32_t r0, uint32_t r1,
                                       uint32_t r2, uint32_t r3) {
    asm volatile("st.shared.v4.b32 [%0], {%1, %2, %3, %4};"
                 :: "r"(addr), "r"(r0), "r"(r1), "r"(r2), "r"(r3) : "memory");
}

__device__ __forceinline__ void ldsm4(uint32_t* r, uint32_t addr) {
    asm volatile("ldmatrix.sync.aligned.m8n8.x4.shared.b16 {%0,%1,%2,%3}, [%4];"
                 : "=r"(r[0]), "=r"(r[1]), "=r"(r[2]), "=r"(r[3]) : "r"(addr));
}

__device__ __forceinline__ void mma16816(float* d, const uint32_t* a, const uint32_t* b) {
    asm volatile("mma.sync.aligned.m16n8k16.row.col.f32.f16.f16.f32 "
                 "{%0,%1,%2,%3}, {%4,%5,%6,%7}, {%8,%9}, {%0,%1,%2,%3};"
                 : "+f"(d[0]), "+f"(d[1]), "+f"(d[2]), "+f"(d[3])
                 : "r"(a[0]), "r"(a[1]), "r"(a[2]), "r"(a[3]),
                   "r"(b[0]), "r"(b[1]));
}

// ---------------------------------------------------------------------------
// Kernel 1 (fused): proj (blocks 0..119) + wsplit (blocks 120..151)
// ---------------------------------------------------------------------------
__global__ __launch_bounds__(256) void prep_kernel(
    const float* __restrict__ seq,
    const float* __restrict__ Wp, const float* __restrict__ bp,
    const float* __restrict__ Wa, const float* __restrict__ ba,
    const float* __restrict__ Wmid)
{
    const int tid = threadIdx.x;
    const int bx = blockIdx.x;

    if (bx >= PROJ_BLOCKS) {
        // ---- wsplit: fp16 hi/lo images, rows padded to 144B ----
        const int idx = bx - PROJ_BLOCKS;
        const int n = idx >> 3, c = (idx >> 1) & 3, half = idx & 1;
        const int j = tid;
        char* imgH = g_w_img + (size_t)((n * NCHUNK + c) * 2) * WIMG_BYTES;
        char* imgL = imgH + WIMG_BYTES;
#pragma unroll 1
        for (int kp = half * 16; kp < half * 16 + 16; kp++) {
            const int k0 = c * KCH + kp * 2;
            const float w0 = Wmid[(n * (H_ + NC_) + k0    ) * H_ + j];
            const float w1 = Wmid[(n * (H_ + NC_) + k0 + 1) * H_ + j];
            const uint32_t h = f16pack(w0, w1);
            const uint32_t l = f16pack(w0 - f16_lo(h), w1 - f16_hi(h));
            *(uint32_t*)(imgH + j * ROWB + kp * 4) = h;
            *(uint32_t*)(imgL + j * ROWB + kp * 4) = l;
        }
        if (half == 0) {
            *(uint4*)(imgH + j * ROWB + 128) = make_uint4(0, 0, 0, 0);
            *(uint4*)(imgL + j * ROWB + 128) = make_uint4(0, 0, 0, 0);
        }
        return;
    }

    // ---- proj: tile 64x64, KC=32, double-buffered ----
    __shared__ __align__(16) float As[2][32][68];   // [buf][k][m] padded
    __shared__ __align__(16) float Bs[2][32][64];   // [buf][k][n]

    const int tx = tid & 15;
    const int ty = tid >> 4;
    const int m0 = (bx / 20) * 64;
    const int n0 = (bx % 20) * 64;

    const float* Wsrc;
    int ld, coff;
    if (n0 < H_) { Wsrc = Wp; ld = H_;        coff = n0; }
    else         { Wsrc = Wa; ld = NC_ * H_;  coff = n0 - H_; }

    const int lm = tid >> 3;
    const int lk = (tid & 7) * 4;

    auto copyB = [&](int kc, int buf) {
        const uint32_t dst = (uint32_t)__cvta_generic_to_shared(&Bs[buf][0][0]);
#pragma unroll
        for (int i = 0; i < 2; i++) {
            const int e = i * 256 + tid;
            const int row = e >> 4, c4 = e & 15;
            cp_async16(dst + (uint32_t)(row * 256 + c4 * 16),
                       Wsrc + (size_t)(kc + row) * ld + coff + c4 * 4);
        }
        cp_commit();
    };
    auto ldgA = [&](int kc, float4* a) {
        a[0] = *(const float4*)(seq + (size_t)(m0 + lm) * D_ + kc + lk);
        a[1] = *(const float4*)(seq + (size_t)(m0 + lm + 32) * D_ + kc + lk);
    };
    auto stsA = [&](const float4* a, int buf) {
#pragma unroll
        for (int j = 0; j < 4; j++) {
            As[buf][lk + j][lm] = ((const float*)&a[0])[j];
            As[buf][lk + j][lm + 32] = ((const float*)&a[1])[j];
        }
    };

    unsigned long long acc2[4][2];
#pragma unroll
    for (int i = 0; i < 4; i++) { acc2[i][0] = 0ull; acc2[i][1] = 0ull; }

    float4 areg[2];
    copyB(0, 0);
    ldgA(0, areg);
    stsA(areg, 0);
    cp_wait_all();
    __syncthreads();

#pragma unroll 1
    for (int c = 0; c < 24; c++) {
        const int buf = c & 1;
        if (c < 23) {
            copyB((c + 1) * 32, buf ^ 1);
            ldgA((c + 1) * 32, areg);
        }
#pragma unroll
        for (int k = 0; k < 32; k++) {
            const float4 a4 = *(const float4*)&As[buf][k][ty * 4];
            const ulonglong2 b2 = *(const ulonglong2*)&Bs[buf][k][tx * 4];
            const unsigned long long pa[4] = {pack2(a4.x), pack2(a4.y),
                                              pack2(a4.z), pack2(a4.w)};
#pragma unroll
            for (int i = 0; i < 4; i++) {
                acc2[i][0] = ffma2(pa[i], b2.x, acc2[i][0]);
                acc2[i][1] = ffma2(pa[i], b2.y, acc2[i][1]);
            }
        }
        if (c < 23) {
            stsA(areg, buf ^ 1);
            cp_wait_all();
            __syncthreads();
        }
    }

#pragma unroll
    for (int i = 0; i < 4; i++) {
        const int r = m0 + ty * 4 + i;
#pragma unroll
        for (int j = 0; j < 2; j++) {
            float lo, hi;
            unpack2(acc2[i][j], lo, hi);
            const int cg = n0 + tx * 4 + j * 2;
            if (cg < H_) {
                g_hp[r * H_ + cg] = lo + bp[cg];
                g_hp[r * H_ + cg + 1] = hi + bp[cg + 1];
            } else {
                const int c2 = cg - H_;
                g_ha[r * (NC_ * H_) + c2] = lo + ba[c2];
                g_ha[r * (NC_ * H_) + c2 + 1] = hi + ba[c2 + 1];
            }
        }
    }
}

// ---------------------------------------------------------------------------
// Kernel 2: refinement via mma.sync m16n8k16 fp16 (X single, W hi/lo -> 2 terms).
// Block (b, n, 8p x 16a): D[128,256] = X[128,256] @ W[256,256] + bs-tail (epi).
// 512 threads = 16 warps, 4(M)x4(N), warp tile 32x64.
// 4-way producer staggering (one producer warp per SMSP at a time).
// ---------------------------------------------------------------------------
__global__ __launch_bounds__(NTHR, 1) void refine_kernel(
    const float* __restrict__ bscore,   // [B, L, NC, L]
    const float* __restrict__ Wmid,     // [NC, H+NC, H]
    const float* __restrict__ bmid,     // [NC, H]
    const float* __restrict__ Wout,     // [NC, H]
    float* __restrict__ out)            // [B, L, NC, L]
{
    extern __shared__ __align__(16) char sm[];
    const uint32_t base = (uint32_t)__cvta_generic_to_shared(sm);

    float* bmid_s  = (float*)(sm + OBMID);
    float* wout_s  = (float*)(sm + OWOUT);
    float* wtail_s = (float*)(sm + OWTAIL);  // [4][256]
    float* part_s  = (float*)(sm + OPART);   // [128][4]

    const int tid = threadIdx.x;
    const int wid = tid >> 5;
    const int lane = tid & 31;
    const int bz = blockIdx.z;
    const int b = bz >> 2, n = bz & 3;
    const int p0 = blockIdx.y * 8;
    const int a0 = blockIdx.x * 16;

    const int mwarp = (wid & 3) * 32;
    const int nwarp = (wid >> 2) * 64;

    // producer group: wid>>2 -> warps {4g..4g+3} = one per SMSP
    const int group = wid >> 2;
    const int gl = (wid & 3) * 32 + lane;    // 0..127 within group

    // epilogue tables
    if (tid < 256) {
        bmid_s[tid] = bmid[n * H_ + tid];
        wout_s[tid] = Wout[n * H_ + tid];
    }
#pragma unroll
    for (int q = 0; q < 2; q++) {
        const int i = q * NTHR + tid;
        wtail_s[i] = Wmid[(n * (H_ + NC_) + H_ + (i >> 8)) * H_ + (i & 255)];
    }

    // build mapping: thread = one m-row (gl), 16 consecutive k per build call
    const int bm = gl;
    const int bp_ = p0 + (bm >> 4);
    const int ba_ = a0 + (bm & 15);
    const float* hp_row = g_hp + (b * L_ + bp_) * H_;
    const float* ha_row = g_ha + ((b * L_ + ba_) * NC_ + n) * H_;

    // lane-constant ldmatrix address offsets
    const uint32_t a_off = (uint32_t)((mwarp + (lane & 15)) * ROWB + ((lane >> 4) << 4));
    const uint32_t b_off = (uint32_t)((nwarp + (lane & 7) + ((lane & 16) ? 8 : 0)) * ROWB
                                      + ((lane & 8) ? 16 : 0));

    // build 16 k-values of chunk c at k-offset qoff (row bm) into buffer buf
    auto buildX_part = [&](int c, int buf, int qoff) {
        const uint32_t xh = base + OXB(buf) + (uint32_t)(bm * ROWB + qoff * 2);
        const float4* hp4 = (const float4*)(hp_row + c * KCH + qoff);
        const float4* ha4 = (const float4*)(ha_row + c * KCH + qoff);
        uint32_t hw[8];
#pragma unroll
        for (int g = 0; g < 4; g++) {
            const float4 u = hp4[g];
            const float4 v = ha4[g];
            const float x0 = htanh(u.x + v.x);
            const float x1 = htanh(u.y + v.y);
            const float x2 = htanh(u.z + v.z);
            const float x3 = htanh(u.w + v.w);
            hw[g * 2 + 0] = f16pack(x0, x1);
            hw[g * 2 + 1] = f16pack(x2, x3);
        }
        sts128(xh,      hw[0], hw[1], hw[2], hw[3]);
        sts128(xh + 16, hw[4], hw[5], hw[6], hw[7]);
    };

    auto copyW = [&](int c, int buf) {
        const char* src = g_w_img + (size_t)((n * NCHUNK + c) * 2) * WIMG_BYTES;
        const uint32_t dst = base + OWB(buf);
#pragma unroll
        for (int i = 0; i < 9; i++) {
            const int e = i * NTHR + tid;
            cp_async16(dst + e * 16, src + (size_t)e * 16);
        }
        cp_commit();
    };

    float acc[2][8][4];
#pragma unroll
    for (int t = 0; t < 2; t++)
#pragma unroll
        for (int q = 0; q < 8; q++)
#pragma unroll
            for (int r = 0; r < 4; r++) acc[t][q][r] = 0.0f;

    // one k16-step: 2 passes of 16 independent MMAs (X*WH, X*WL)
    auto mma_ks = [&](int ks, uint32_t xb, uint32_t wb) {
        uint32_t A0[4], A1[4], BH[4][4], BL[4][4];
        const uint32_t kb = (uint32_t)(ks * 32);
        ldsm4(A0, xb + a_off + kb);
        ldsm4(A1, xb + a_off + 16 * ROWB + kb);
#pragma unroll
        for (int q = 0; q < 4; q++)
            ldsm4(BH[q], wb + b_off + q * 16 * ROWB + kb);
#pragma unroll
        for (int q = 0; q < 4; q++)
            ldsm4(BL[q], wb + 36864 + b_off + q * 16 * ROWB + kb);
        // pass 1: X x WH
#pragma unroll
        for (int q2 = 0; q2 < 8; q2++) {
            const uint32_t* bq = &BH[q2 >> 1][(q2 & 1) * 2];
            mma16816(acc[0][q2], A0, bq);
            mma16816(acc[1][q2], A1, bq);
        }
        // pass 2: X x WL
#pragma unroll
        for (int q2 = 0; q2 < 8; q2++) {
            const uint32_t* bq = &BL[q2 >> 1][(q2 & 1) * 2];
            mma16816(acc[0][q2], A0, bq);
            mma16816(acc[1][q2], A1, bq);
        }
    };

    // ---- prologue: each group builds its quarter of chunk 0 ----
    copyW(0, 0);
    buildX_part(0, 0, group * 16);
    cp_wait_all();
    __syncthreads();

#pragma unroll 1
    for (int c = 0; c < NCHUNK; c++) {
        const int cur = c & 1;
        const uint32_t xb = base + OXB(cur);
        const uint32_t wb = base + OWB(cur);
        const bool more = (c < NCHUNK - 1);
        if (more) copyW(c + 1, cur ^ 1);
        mma_ks(0, xb, wb);
        if (more && group == 0) buildX_part(c + 1, cur ^ 1, 0);
        mma_ks(1, xb, wb);
        if (more && group == 1) buildX_part(c + 1, cur ^ 1, 16);
        if (more && group == 3) buildX_part(c + 1, cur ^ 1, 48);
        mma_ks(2, xb, wb);
        if (more && group == 2) buildX_part(c + 1, cur ^ 1, 32);
        mma_ks(3, xb, wb);
        if (more) {
            cp_wait_all();
            __syncthreads();
        }
    }

    // ---- epilogue: +bs-tail +bmid, tanh, dot Wout, reduce over N ----
    const int g = lane >> 2;
    float bsv[2][2][4];
#pragma unroll
    for (int t = 0; t < 2; t++)
#pragma unroll
        for (int h = 0; h < 2; h++) {
            const int row = mwarp + t * 16 + g + h * 8;
            const float* bsp = bscore
                + ((b * L_ + p0 + (row >> 4)) * NC_) * L_ + a0 + (row & 15);
#pragma unroll
            for (int ct = 0; ct < 4; ct++) bsv[t][h][ct] = bsp[ct * L_];
        }

    float part[2][2] = {{0.0f, 0.0f}, {0.0f, 0.0f}};
#pragma unroll
    for (int q2 = 0; q2 < 8; q2++) {
        const int j0 = nwarp + q2 * 8 + (lane & 3) * 2;
        const float bm0 = bmid_s[j0], bm1 = bmid_s[j0 + 1];
        const float wo0 = wout_s[j0], wo1 = wout_s[j0 + 1];
        float wt0[4], wt1[4];
#pragma unroll
        for (int ct = 0; ct < 4; ct++) {
            wt0[ct] = wtail_s[ct * 256 + j0];
            wt1[ct] = wtail_s[ct * 256 + j0 + 1];
        }
#pragma unroll
        for (int t = 0; t < 2; t++)
#pragma unroll
            for (int h = 0; h < 2; h++) {
                float v0 = acc[t][q2][h * 2 + 0] + bm0;
                float v1 = acc[t][q2][h * 2 + 1] + bm1;
#pragma unroll
                for (int ct = 0; ct < 4; ct++) {
                    v0 = fmaf(bsv[t][h][ct], wt0[ct], v0);
                    v1 = fmaf(bsv[t][h][ct], wt1[ct], v1);
                }
                part[t][h] = fmaf(htanh(v0), wo0, part[t][h]);
                part[t][h] = fmaf(htanh(v1), wo1, part[t][h]);
            }
    }
#pragma unroll
    for (int t = 0; t < 2; t++)
#pragma unroll
        for (int h = 0; h < 2; h++) {
            float v = part[t][h];
            v += __shfl_xor_sync(0xFFFFFFFFu, v, 1, 4);
            v += __shfl_xor_sync(0xFFFFFFFFu, v, 2, 4);
            if ((lane & 3) == 0) {
                const int row = mwarp + t * 16 + g + h * 8;
                part_s[row * 4 + (wid >> 2)] = v;
            }
        }
    __syncthreads();

    if (tid < 128) {
        const float s = part_s[tid * 4] + part_s[tid * 4 + 1]
                      + part_s[tid * 4 + 2] + part_s[tid * 4 + 3];
        const int p = p0 + (tid >> 4);
        const int a = a0 + (tid & 15);
        out[((b * L_ + p) * NC_ + n) * L_ + a] = s;
    }
}

// ---------------------------------------------------------------------------
// Launch
// ---------------------------------------------------------------------------
extern "C" void kernel_launch(void* const* d_in, const int* in_sizes, int n_in,
                              void* d_out, int out_size) {
    const float* seq    = (const float*)d_in[0];
    const float* bscore = (const float*)d_in[1];
    const float* Wp     = (const float*)d_in[2];
    const float* bp     = (const float*)d_in[3];
    const float* Wa     = (const float*)d_in[4];
    const float* ba     = (const float*)d_in[5];
    const float* Wmid   = (const float*)d_in[6];
    const float* bmid   = (const float*)d_in[7];
    const float* Wout   = (const float*)d_in[8];
    float* out = (float*)d_out;

    prep_kernel<<<PREP_BLOCKS, 256>>>(seq, Wp, bp, Wa, ba, Wmid);

    cudaFuncSetAttribute(refine_kernel,
                         cudaFuncAttributeMaxDynamicSharedMemorySize, SMEM_BYTES);
    refine_kernel<<<dim3(L_ / 16, L_ / 8, B_ * NC_), NTHR, SMEM_BYTES>>>(
        bscore, Wmid, bmid, Wout, out);
}

// round 12
// speedup vs baseline: 1.8250x; 1.2977x over previous
#include <cuda_runtime.h>
#include <cuda_fp16.h>
#include <cstdint>

// Problem constants (fixed by the dataset)
#define B_  2
#define L_  192
#define D_  768
#define NC_ 4
#define H_  256

#define KCH     64              // k per chunk in refine
#define NCHUNK  4               // K = 256 = 4 x 64 (bs tail folded into epilogue)
#define NTHR    512             // refine threads (16 warps)
#define ROWB    144             // padded row stride: 64 fp16 = 128B + 16B pad

#define WIMG_BYTES (256 * ROWB) // one W image: 256 n-rows x 144B

// Refine SMEM layout (byte offsets into dynamic smem)
#define OXB(buf)  ((buf) * 18432)            // X bufs (fp16)
#define OWB(buf)  (36864 + (buf) * 36864)    // W bufs (fp16, single image)
#define OBMID     110592
#define OWOUT     111616
#define OWTAIL    112640                      // float[4][256]
#define OPART     116736                      // float[128][4]
#define SMEM_BYTES 118784

#define PROJ_BLOCKS 120   // 6 m-tiles x 20 n-tiles
#define PREP_BLOCKS (PROJ_BLOCKS + 32)

// Scratch (no cudaMalloc allowed)
__device__ float g_hp[B_ * L_ * H_];                 // [B*L, H]
__device__ float g_ha[B_ * L_ * NC_ * H_];           // [B*L, NC*H]
__device__ __align__(16) char g_w_img[NC_ * NCHUNK * WIMG_BYTES];

// ---------------------------------------------------------------------------
// Helpers
// ---------------------------------------------------------------------------
// Hardware tanh: single MUFU.TANH op (sm_75+ baseline PTX).
__device__ __forceinline__ float htanh(float x) {
    float y;
    asm("tanh.approx.f32 %0, %1;" : "=f"(y) : "f"(x));
    return y;
}

// pack two floats to fp16x2: LOW half = a, HIGH half = b
__device__ __forceinline__ uint32_t f16pack(float a, float b) {
    const __half2 h = __floats2half2_rn(a, b);
    return *(const uint32_t*)&h;
}

__device__ __forceinline__ unsigned long long pack2(float x) {
    unsigned long long r;
    asm("mov.b64 %0, {%1, %1};" : "=l"(r) : "f"(x));
    return r;
}
__device__ __forceinline__ unsigned long long ffma2(unsigned long long a,
                                                    unsigned long long b,
                                                    unsigned long long c) {
    unsigned long long d;
    asm("fma.rn.f32x2 %0, %1, %2, %3;" : "=l"(d) : "l"(a), "l"(b), "l"(c));
    return d;
}
__device__ __forceinline__ void unpack2(unsigned long long v, float& lo, float& hi) {
    asm("mov.b64 {%0, %1}, %2;" : "=f"(lo), "=f"(hi) : "l"(v));
}

__device__ __forceinline__ void cp_async16(uint32_t smem, const void* gptr) {
    asm volatile("cp.async.cg.shared.global [%0], [%1], 16;" :: "r"(smem), "l"(gptr));
}
__device__ __forceinline__ void cp_commit() { asm volatile("cp.async.commit_group;"); }
__device__ __forceinline__ void cp_wait_all() { asm volatile("cp.async.wait_group 0;" ::: "memory"); }

__device__ __forceinline__ void sts128(uint32_t addr, uint32_t r0, uint32_t r1,
                                       uint32_t r2, uint32_t r3) {
    asm volatile("st.shared.v4.b32 [%0], {%1, %2, %3, %4};"
                 :: "r"(addr), "r"(r0), "r"(r1), "r"(r2), "r"(r3) : "memory");
}

__device__ __forceinline__ void ldsm4(uint32_t* r, uint32_t addr) {
    asm volatile("ldmatrix.sync.aligned.m8n8.x4.shared.b16 {%0,%1,%2,%3}, [%4];"
                 : "=r"(r[0]), "=r"(r[1]), "=r"(r[2]), "=r"(r[3]) : "r"(addr));
}

__device__ __forceinline__ void mma16816(float* d, const uint32_t* a, const uint32_t* b) {
    asm volatile("mma.sync.aligned.m16n8k16.row.col.f32.f16.f16.f32 "
                 "{%0,%1,%2,%3}, {%4,%5,%6,%7}, {%8,%9}, {%0,%1,%2,%3};"
                 : "+f"(d[0]), "+f"(d[1]), "+f"(d[2]), "+f"(d[3])
                 : "r"(a[0]), "r"(a[1]), "r"(a[2]), "r"(a[3]),
                   "r"(b[0]), "r"(b[1]));
}

// ---------------------------------------------------------------------------
// Kernel 1 (fused): proj (blocks 0..119) + wsplit (blocks 120..151)
// ---------------------------------------------------------------------------
__global__ __launch_bounds__(256) void prep_kernel(
    const float* __restrict__ seq,
    const float* __restrict__ Wp, const float* __restrict__ bp,
    const float* __restrict__ Wa, const float* __restrict__ ba,
    const float* __restrict__ Wmid)
{
    const int tid = threadIdx.x;
    const int bx = blockIdx.x;

    if (bx >= PROJ_BLOCKS) {
        // ---- wsplit: fp16 image, rows padded to 144B ----
        const int idx = bx - PROJ_BLOCKS;
        const int n = idx >> 3, c = (idx >> 1) & 3, half = idx & 1;
        const int j = tid;
        char* img = g_w_img + (size_t)(n * NCHUNK + c) * WIMG_BYTES;
#pragma unroll 1
        for (int kp = half * 16; kp < half * 16 + 16; kp++) {
            const int k0 = c * KCH + kp * 2;
            const float w0 = Wmid[(n * (H_ + NC_) + k0    ) * H_ + j];
            const float w1 = Wmid[(n * (H_ + NC_) + k0 + 1) * H_ + j];
            *(uint32_t*)(img + j * ROWB + kp * 4) = f16pack(w0, w1);
        }
        if (half == 0)
            *(uint4*)(img + j * ROWB + 128) = make_uint4(0, 0, 0, 0);
        return;
    }

    // ---- proj: tile 64x64, KC=32, double-buffered ----
    __shared__ __align__(16) float As[2][32][68];   // [buf][k][m] padded
    __shared__ __align__(16) float Bs[2][32][64];   // [buf][k][n]

    const int tx = tid & 15;
    const int ty = tid >> 4;
    const int m0 = (bx / 20) * 64;
    const int n0 = (bx % 20) * 64;

    const float* Wsrc;
    int ld, coff;
    if (n0 < H_) { Wsrc = Wp; ld = H_;        coff = n0; }
    else         { Wsrc = Wa; ld = NC_ * H_;  coff = n0 - H_; }

    const int lm = tid >> 3;
    const int lk = (tid & 7) * 4;

    auto copyB = [&](int kc, int buf) {
        const uint32_t dst = (uint32_t)__cvta_generic_to_shared(&Bs[buf][0][0]);
#pragma unroll
        for (int i = 0; i < 2; i++) {
            const int e = i * 256 + tid;
            const int row = e >> 4, c4 = e & 15;
            cp_async16(dst + (uint32_t)(row * 256 + c4 * 16),
                       Wsrc + (size_t)(kc + row) * ld + coff + c4 * 4);
        }
        cp_commit();
    };
    auto ldgA = [&](int kc, float4* a) {
        a[0] = *(const float4*)(seq + (size_t)(m0 + lm) * D_ + kc + lk);
        a[1] = *(const float4*)(seq + (size_t)(m0 + lm + 32) * D_ + kc + lk);
    };
    auto stsA = [&](const float4* a, int buf) {
#pragma unroll
        for (int j = 0; j < 4; j++) {
            As[buf][lk + j][lm] = ((const float*)&a[0])[j];
            As[buf][lk + j][lm + 32] = ((const float*)&a[1])[j];
        }
    };

    unsigned long long acc2[4][2];
#pragma unroll
    for (int i = 0; i < 4; i++) { acc2[i][0] = 0ull; acc2[i][1] = 0ull; }

    float4 areg[2];
    copyB(0, 0);
    ldgA(0, areg);
    stsA(areg, 0);
    cp_wait_all();
    __syncthreads();

#pragma unroll 1
    for (int c = 0; c < 24; c++) {
        const int buf = c & 1;
        if (c < 23) {
            copyB((c + 1) * 32, buf ^ 1);
            ldgA((c + 1) * 32, areg);
        }
#pragma unroll
        for (int k = 0; k < 32; k++) {
            const float4 a4 = *(const float4*)&As[buf][k][ty * 4];
            const ulonglong2 b2 = *(const ulonglong2*)&Bs[buf][k][tx * 4];
            const unsigned long long pa[4] = {pack2(a4.x), pack2(a4.y),
                                              pack2(a4.z), pack2(a4.w)};
#pragma unroll
            for (int i = 0; i < 4; i++) {
                acc2[i][0] = ffma2(pa[i], b2.x, acc2[i][0]);
                acc2[i][1] = ffma2(pa[i], b2.y, acc2[i][1]);
            }
        }
        if (c < 23) {
            stsA(areg, buf ^ 1);
            cp_wait_all();
            __syncthreads();
        }
    }

#pragma unroll
    for (int i = 0; i < 4; i++) {
        const int r = m0 + ty * 4 + i;
#pragma unroll
        for (int j = 0; j < 2; j++) {
            float lo, hi;
            unpack2(acc2[i][j], lo, hi);
            const int cg = n0 + tx * 4 + j * 2;
            if (cg < H_) {
                g_hp[r * H_ + cg] = lo + bp[cg];
                g_hp[r * H_ + cg + 1] = hi + bp[cg + 1];
            } else {
                const int c2 = cg - H_;
                g_ha[r * (NC_ * H_) + c2] = lo + ba[c2];
                g_ha[r * (NC_ * H_) + c2 + 1] = hi + ba[c2 + 1];
            }
        }
    }
}

// ---------------------------------------------------------------------------
// Kernel 2: refinement via mma.sync m16n8k16 fp16 (X and W single fp16).
// Block (b, n, 8p x 16a): D[128,256] = X[128,256] @ W[256,256] + bs-tail (epi).
// 512 threads = 16 warps, 4(M)x4(N), warp tile 32x64.
// 4-way producer staggering (one producer warp per SMSP at a time).
// ---------------------------------------------------------------------------
__global__ __launch_bounds__(NTHR, 1) void refine_kernel(
    const float* __restrict__ bscore,   // [B, L, NC, L]
    const float* __restrict__ Wmid,     // [NC, H+NC, H]
    const float* __restrict__ bmid,     // [NC, H]
    const float* __restrict__ Wout,     // [NC, H]
    float* __restrict__ out)            // [B, L, NC, L]
{
    extern __shared__ __align__(16) char sm[];
    const uint32_t base = (uint32_t)__cvta_generic_to_shared(sm);

    float* bmid_s  = (float*)(sm + OBMID);
    float* wout_s  = (float*)(sm + OWOUT);
    float* wtail_s = (float*)(sm + OWTAIL);  // [4][256]
    float* part_s  = (float*)(sm + OPART);   // [128][4]

    const int tid = threadIdx.x;
    const int wid = tid >> 5;
    const int lane = tid & 31;
    const int bz = blockIdx.z;
    const int b = bz >> 2, n = bz & 3;
    const int p0 = blockIdx.y * 8;
    const int a0 = blockIdx.x * 16;

    const int mwarp = (wid & 3) * 32;
    const int nwarp = (wid >> 2) * 64;

    // producer group: wid>>2 -> warps {4g..4g+3} = one per SMSP
    const int group = wid >> 2;
    const int gl = (wid & 3) * 32 + lane;    // 0..127 within group

    // epilogue tables
    if (tid < 256) {
        bmid_s[tid] = bmid[n * H_ + tid];
        wout_s[tid] = Wout[n * H_ + tid];
    }
#pragma unroll
    for (int q = 0; q < 2; q++) {
        const int i = q * NTHR + tid;
        wtail_s[i] = Wmid[(n * (H_ + NC_) + H_ + (i >> 8)) * H_ + (i & 255)];
    }

    // build mapping: thread = one m-row (gl), 16 consecutive k per build call
    const int bm = gl;
    const int bp_ = p0 + (bm >> 4);
    const int ba_ = a0 + (bm & 15);
    const float* hp_row = g_hp + (b * L_ + bp_) * H_;
    const float* ha_row = g_ha + ((b * L_ + ba_) * NC_ + n) * H_;

    // lane-constant ldmatrix address offsets
    const uint32_t a_off = (uint32_t)((mwarp + (lane & 15)) * ROWB + ((lane >> 4) << 4));
    const uint32_t b_off = (uint32_t)((nwarp + (lane & 7) + ((lane & 16) ? 8 : 0)) * ROWB
                                      + ((lane & 8) ? 16 : 0));

    // build 16 k-values of chunk c at k-offset qoff (row bm) into buffer buf
    auto buildX_part = [&](int c, int buf, int qoff) {
        const uint32_t xh = base + OXB(buf) + (uint32_t)(bm * ROWB + qoff * 2);
        const float4* hp4 = (const float4*)(hp_row + c * KCH + qoff);
        const float4* ha4 = (const float4*)(ha_row + c * KCH + qoff);
        uint32_t hw[8];
#pragma unroll
        for (int g = 0; g < 4; g++) {
            const float4 u = hp4[g];
            const float4 v = ha4[g];
            const float x0 = htanh(u.x + v.x);
            const float x1 = htanh(u.y + v.y);
            const float x2 = htanh(u.z + v.z);
            const float x3 = htanh(u.w + v.w);
            hw[g * 2 + 0] = f16pack(x0, x1);
            hw[g * 2 + 1] = f16pack(x2, x3);
        }
        sts128(xh,      hw[0], hw[1], hw[2], hw[3]);
        sts128(xh + 16, hw[4], hw[5], hw[6], hw[7]);
    };

    auto copyW = [&](int c, int buf) {
        const char* src = g_w_img + (size_t)(n * NCHUNK + c) * WIMG_BYTES;
        const uint32_t dst = base + OWB(buf);
#pragma unroll
        for (int i = 0; i < 4; i++) {
            const int e = i * NTHR + tid;
            cp_async16(dst + e * 16, src + (size_t)e * 16);
        }
        // remainder: 2304 16B-chunks total, 2048 done above
        if (tid < 256) {
            const int e = 4 * NTHR + tid;
            cp_async16(dst + e * 16, src + (size_t)e * 16);
        }
        cp_commit();
    };

    float acc[2][8][4];
#pragma unroll
    for (int t = 0; t < 2; t++)
#pragma unroll
        for (int q = 0; q < 8; q++)
#pragma unroll
            for (int r = 0; r < 4; r++) acc[t][q][r] = 0.0f;

    // one k16-step: 16 independent MMAs
    auto mma_ks = [&](int ks, uint32_t xb, uint32_t wb) {
        uint32_t A0[4], A1[4], BH[4][4];
        const uint32_t kb = (uint32_t)(ks * 32);
        ldsm4(A0, xb + a_off + kb);
        ldsm4(A1, xb + a_off + 16 * ROWB + kb);
#pragma unroll
        for (int q = 0; q < 4; q++)
            ldsm4(BH[q], wb + b_off + q * 16 * ROWB + kb);
#pragma unroll
        for (int q2 = 0; q2 < 8; q2++) {
            const uint32_t* bq = &BH[q2 >> 1][(q2 & 1) * 2];
            mma16816(acc[0][q2], A0, bq);
            mma16816(acc[1][q2], A1, bq);
        }
    };

    // ---- prologue: each group builds its quarter of chunk 0 ----
    copyW(0, 0);
    buildX_part(0, 0, group * 16);
    cp_wait_all();
    __syncthreads();

#pragma unroll 1
    for (int c = 0; c < NCHUNK; c++) {
        const int cur = c & 1;
        const uint32_t xb = base + OXB(cur);
        const uint32_t wb = base + OWB(cur);
        const bool more = (c < NCHUNK - 1);
        if (more) copyW(c + 1, cur ^ 1);
        mma_ks(0, xb, wb);
        if (more && group == 0) buildX_part(c + 1, cur ^ 1, 0);
        mma_ks(1, xb, wb);
        if (more && group == 1) buildX_part(c + 1, cur ^ 1, 16);
        if (more && group == 3) buildX_part(c + 1, cur ^ 1, 48);
        mma_ks(2, xb, wb);
        if (more && group == 2) buildX_part(c + 1, cur ^ 1, 32);
        mma_ks(3, xb, wb);
        if (more) {
            cp_wait_all();
            __syncthreads();
        }
    }

    // ---- epilogue: +bs-tail +bmid, tanh, dot Wout, reduce over N ----
    const int g = lane >> 2;
    float bsv[2][2][4];
#pragma unroll
    for (int t = 0; t < 2; t++)
#pragma unroll
        for (int h = 0; h < 2; h++) {
            const int row = mwarp + t * 16 + g + h * 8;
            const float* bsp = bscore
                + ((b * L_ + p0 + (row >> 4)) * NC_) * L_ + a0 + (row & 15);
#pragma unroll
            for (int ct = 0; ct < 4; ct++) bsv[t][h][ct] = bsp[ct * L_];
        }

    float part[2][2] = {{0.0f, 0.0f}, {0.0f, 0.0f}};
#pragma unroll
    for (int q2 = 0; q2 < 8; q2++) {
        const int j0 = nwarp + q2 * 8 + (lane & 3) * 2;
        const float bm0 = bmid_s[j0], bm1 = bmid_s[j0 + 1];
        const float wo0 = wout_s[j0], wo1 = wout_s[j0 + 1];
        float wt0[4], wt1[4];
#pragma unroll
        for (int ct = 0; ct < 4; ct++) {
            wt0[ct] = wtail_s[ct * 256 + j0];
            wt1[ct] = wtail_s[ct * 256 + j0 + 1];
        }
#pragma unroll
        for (int t = 0; t < 2; t++)
#pragma unroll
            for (int h = 0; h < 2; h++) {
                float v0 = acc[t][q2][h * 2 + 0] + bm0;
                float v1 = acc[t][q2][h * 2 + 1] + bm1;
#pragma unroll
                for (int ct = 0; ct < 4; ct++) {
                    v0 = fmaf(bsv[t][h][ct], wt0[ct], v0);
                    v1 = fmaf(bsv[t][h][ct], wt1[ct], v1);
                }
                part[t][h] = fmaf(htanh(v0), wo0, part[t][h]);
                part[t][h] = fmaf(htanh(v1), wo1, part[t][h]);
            }
    }
#pragma unroll
    for (int t = 0; t < 2; t++)
#pragma unroll
        for (int h = 0; h < 2; h++) {
            float v = part[t][h];
            v += __shfl_xor_sync(0xFFFFFFFFu, v, 1, 4);
            v += __shfl_xor_sync(0xFFFFFFFFu, v, 2, 4);
            if ((lane & 3) == 0) {
                const int row = mwarp + t * 16 + g + h * 8;
                part_s[row * 4 + (wid >> 2)] = v;
            }
        }
    __syncthreads();

    if (tid < 128) {
        const float s = part_s[tid * 4] + part_s[tid * 4 + 1]
                      + part_s[tid * 4 + 2] + part_s[tid * 4 + 3];
        const int p = p0 + (tid >> 4);
        const int a = a0 + (tid & 15);
        out[((b * L_ + p) * NC_ + n) * L_ + a] = s;
    }
}

// ---------------------------------------------------------------------------
// Launch
// ---------------------------------------------------------------------------
extern "C" void kernel_launch(void* const* d_in, const int* in_sizes, int n_in,
                              void* d_out, int out_size) {
    const float* seq    = (const float*)d_in[0];
    const float* bscore = (const float*)d_in[1];
    const float* Wp     = (const float*)d_in[2];
    const float* bp     = (const float*)d_in[3];
    const float* Wa     = (const float*)d_in[4];
    const float* ba     = (const float*)d_in[5];
    const float* Wmid   = (const float*)d_in[6];
    const float* bmid   = (const float*)d_in[7];
    const float* Wout   = (const float*)d_in[8];
    float* out = (float*)d_out;

    prep_kernel<<<PREP_BLOCKS, 256>>>(seq, Wp, bp, Wa, ba, Wmid);

    cudaFuncSetAttribute(refine_kernel,
                         cudaFuncAttributeMaxDynamicSharedMemorySize, SMEM_BYTES);
    refine_kernel<<<dim3(L_ / 16, L_ / 8, B_ * NC_), NTHR, SMEM_BYTES>>>(
        bscore, Wmid, bmid, Wout, out);
}

// round 13
// speedup vs baseline: 2.3173x; 1.2697x over previous
#include <cuda_runtime.h>
#include <cuda_fp16.h>
#include <cstdint>

// Problem constants (fixed by the dataset)
#define B_  2
#define L_  192
#define D_  768
#define NC_ 4
#define H_  256

#define KCH     64              // k per chunk in refine
#define NCHUNK  4               // K = 256 = 4 x 64 (bs tail folded into epilogue)
#define NTHR    512             // refine threads (16 warps)
#define ROWB    144             // padded row stride: 64 fp16 = 128B + 16B pad

#define WIMG_BYTES (256 * ROWB) // one W image: 256 n-rows x 144B

// Refine SMEM layout (byte offsets into dynamic smem)
#define OXB(buf)  ((buf) * 18432)            // X bufs (fp16)
#define OWB(buf)  (36864 + (buf) * 36864)    // W bufs (fp16, single image)
#define OBMID     110592
#define OWOUT     111616
#define OWTAIL    112640                      // float[4][256]
#define OPART     116736                      // float[128][4]
#define SMEM_BYTES 118784

#define PROJ_BLOCKS 120   // 6 m-tiles x 20 n-tiles
#define PREP_BLOCKS (PROJ_BLOCKS + 32)

// Scratch (no cudaMalloc allowed)
__device__ float g_hp[B_ * L_ * H_];                 // [B*L, H]
__device__ float g_ha[B_ * L_ * NC_ * H_];           // [B*L, NC*H]
__device__ __align__(16) char g_w_img[NC_ * NCHUNK * WIMG_BYTES];

// ---------------------------------------------------------------------------
// Helpers
// ---------------------------------------------------------------------------
// Hardware tanh: single MUFU.TANH op (sm_75+ baseline PTX).
__device__ __forceinline__ float htanh(float x) {
    float y;
    asm("tanh.approx.f32 %0, %1;" : "=f"(y) : "f"(x));
    return y;
}

// pack two floats to fp16x2: LOW half = a, HIGH half = b
__device__ __forceinline__ uint32_t f16pack(float a, float b) {
    const __half2 h = __floats2half2_rn(a, b);
    return *(const uint32_t*)&h;
}

__device__ __forceinline__ unsigned long long pack2(float x) {
    unsigned long long r;
    asm("mov.b64 %0, {%1, %1};" : "=l"(r) : "f"(x));
    return r;
}
__device__ __forceinline__ unsigned long long ffma2(unsigned long long a,
                                                    unsigned long long b,
                                                    unsigned long long c) {
    unsigned long long d;
    asm("fma.rn.f32x2 %0, %1, %2, %3;" : "=l"(d) : "l"(a), "l"(b), "l"(c));
    return d;
}
__device__ __forceinline__ void unpack2(unsigned long long v, float& lo, float& hi) {
    asm("mov.b64 {%0, %1}, %2;" : "=f"(lo), "=f"(hi) : "l"(v));
}

__device__ __forceinline__ void cp_async16(uint32_t smem, const void* gptr) {
    asm volatile("cp.async.cg.shared.global [%0], [%1], 16;" :: "r"(smem), "l"(gptr));
}
__device__ __forceinline__ void cp_commit() { asm volatile("cp.async.commit_group;"); }
__device__ __forceinline__ void cp_wait_all() { asm volatile("cp.async.wait_group 0;" ::: "memory"); }

__device__ __forceinline__ void sts64(uint32_t addr, uint32_t r0, uint32_t r1) {
    asm volatile("st.shared.v2.b32 [%0], {%1, %2};"
                 :: "r"(addr), "r"(r0), "r"(r1) : "memory");
}

__device__ __forceinline__ void ldsm4(uint32_t* r, uint32_t addr) {
    asm volatile("ldmatrix.sync.aligned.m8n8.x4.shared.b16 {%0,%1,%2,%3}, [%4];"
                 : "=r"(r[0]), "=r"(r[1]), "=r"(r[2]), "=r"(r[3]) : "r"(addr));
}

__device__ __forceinline__ void mma16816(float* d, const uint32_t* a, const uint32_t* b) {
    asm volatile("mma.sync.aligned.m16n8k16.row.col.f32.f16.f16.f32 "
                 "{%0,%1,%2,%3}, {%4,%5,%6,%7}, {%8,%9}, {%0,%1,%2,%3};"
                 : "+f"(d[0]), "+f"(d[1]), "+f"(d[2]), "+f"(d[3])
                 : "r"(a[0]), "r"(a[1]), "r"(a[2]), "r"(a[3]),
                   "r"(b[0]), "r"(b[1]));
}

// ---------------------------------------------------------------------------
// Kernel 1 (fused): proj (blocks 0..119) + wsplit (blocks 120..151)
// ---------------------------------------------------------------------------
__global__ __launch_bounds__(256) void prep_kernel(
    const float* __restrict__ seq,
    const float* __restrict__ Wp, const float* __restrict__ bp,
    const float* __restrict__ Wa, const float* __restrict__ ba,
    const float* __restrict__ Wmid)
{
    const int tid = threadIdx.x;
    const int bx = blockIdx.x;

    if (bx >= PROJ_BLOCKS) {
        // ---- wsplit: fp16 image, rows padded to 144B ----
        const int idx = bx - PROJ_BLOCKS;
        const int n = idx >> 3, c = (idx >> 1) & 3, half = idx & 1;
        const int j = tid;
        char* img = g_w_img + (size_t)(n * NCHUNK + c) * WIMG_BYTES;
#pragma unroll 1
        for (int kp = half * 16; kp < half * 16 + 16; kp++) {
            const int k0 = c * KCH + kp * 2;
            const float w0 = Wmid[(n * (H_ + NC_) + k0    ) * H_ + j];
            const float w1 = Wmid[(n * (H_ + NC_) + k0 + 1) * H_ + j];
            *(uint32_t*)(img + j * ROWB + kp * 4) = f16pack(w0, w1);
        }
        if (half == 0)
            *(uint4*)(img + j * ROWB + 128) = make_uint4(0, 0, 0, 0);
        return;
    }

    // ---- proj: tile 64x64, KC=32, double-buffered ----
    __shared__ __align__(16) float As[2][32][68];   // [buf][k][m] padded
    __shared__ __align__(16) float Bs[2][32][64];   // [buf][k][n]

    const int tx = tid & 15;
    const int ty = tid >> 4;
    const int m0 = (bx / 20) * 64;
    const int n0 = (bx % 20) * 64;

    const float* Wsrc;
    int ld, coff;
    if (n0 < H_) { Wsrc = Wp; ld = H_;        coff = n0; }
    else         { Wsrc = Wa; ld = NC_ * H_;  coff = n0 - H_; }

    const int lm = tid >> 3;
    const int lk = (tid & 7) * 4;

    auto copyB = [&](int kc, int buf) {
        const uint32_t dst = (uint32_t)__cvta_generic_to_shared(&Bs[buf][0][0]);
#pragma unroll
        for (int i = 0; i < 2; i++) {
            const int e = i * 256 + tid;
            const int row = e >> 4, c4 = e & 15;
            cp_async16(dst + (uint32_t)(row * 256 + c4 * 16),
                       Wsrc + (size_t)(kc + row) * ld + coff + c4 * 4);
        }
        cp_commit();
    };
    auto ldgA = [&](int kc, float4* a) {
        a[0] = *(const float4*)(seq + (size_t)(m0 + lm) * D_ + kc + lk);
        a[1] = *(const float4*)(seq + (size_t)(m0 + lm + 32) * D_ + kc + lk);
    };
    auto stsA = [&](const float4* a, int buf) {
#pragma unroll
        for (int j = 0; j < 4; j++) {
            As[buf][lk + j][lm] = ((const float*)&a[0])[j];
            As[buf][lk + j][lm + 32] = ((const float*)&a[1])[j];
        }
    };

    unsigned long long acc2[4][2];
#pragma unroll
    for (int i = 0; i < 4; i++) { acc2[i][0] = 0ull; acc2[i][1] = 0ull; }

    float4 areg[2];
    copyB(0, 0);
    ldgA(0, areg);
    stsA(areg, 0);
    cp_wait_all();
    __syncthreads();

#pragma unroll 1
    for (int c = 0; c < 24; c++) {
        const int buf = c & 1;
        if (c < 23) {
            copyB((c + 1) * 32, buf ^ 1);
            ldgA((c + 1) * 32, areg);
        }
#pragma unroll
        for (int k = 0; k < 32; k++) {
            const float4 a4 = *(const float4*)&As[buf][k][ty * 4];
            const ulonglong2 b2 = *(const ulonglong2*)&Bs[buf][k][tx * 4];
            const unsigned long long pa[4] = {pack2(a4.x), pack2(a4.y),
                                              pack2(a4.z), pack2(a4.w)};
#pragma unroll
            for (int i = 0; i < 4; i++) {
                acc2[i][0] = ffma2(pa[i], b2.x, acc2[i][0]);
                acc2[i][1] = ffma2(pa[i], b2.y, acc2[i][1]);
            }
        }
        if (c < 23) {
            stsA(areg, buf ^ 1);
            cp_wait_all();
            __syncthreads();
        }
    }

#pragma unroll
    for (int i = 0; i < 4; i++) {
        const int r = m0 + ty * 4 + i;
#pragma unroll
        for (int j = 0; j < 2; j++) {
            float lo, hi;
            unpack2(acc2[i][j], lo, hi);
            const int cg = n0 + tx * 4 + j * 2;
            if (cg < H_) {
                g_hp[r * H_ + cg] = lo + bp[cg];
                g_hp[r * H_ + cg + 1] = hi + bp[cg + 1];
            } else {
                const int c2 = cg - H_;
                g_ha[r * (NC_ * H_) + c2] = lo + ba[c2];
                g_ha[r * (NC_ * H_) + c2 + 1] = hi + ba[c2 + 1];
            }
        }
    }
}

// ---------------------------------------------------------------------------
// Kernel 2: refinement via mma.sync m16n8k16 fp16 (X and W single fp16).
// Block (b, n, 8p x 16a): D[128,256] = X[128,256] @ W[256,256] + bs-tail (epi).
// 512 threads = 16 warps, 4(M)x4(N), warp tile 32x64.
// 4-way producer staggering; build reads coalesced 4-lanes-per-row (nL=8).
// ---------------------------------------------------------------------------
__global__ __launch_bounds__(NTHR, 1) void refine_kernel(
    const float* __restrict__ bscore,   // [B, L, NC, L]
    const float* __restrict__ Wmid,     // [NC, H+NC, H]
    const float* __restrict__ bmid,     // [NC, H]
    const float* __restrict__ Wout,     // [NC, H]
    float* __restrict__ out)            // [B, L, NC, L]
{
    extern __shared__ __align__(16) char sm[];
    const uint32_t base = (uint32_t)__cvta_generic_to_shared(sm);

    float* bmid_s  = (float*)(sm + OBMID);
    float* wout_s  = (float*)(sm + OWOUT);
    float* wtail_s = (float*)(sm + OWTAIL);  // [4][256]
    float* part_s  = (float*)(sm + OPART);   // [128][4]

    const int tid = threadIdx.x;
    const int wid = tid >> 5;
    const int lane = tid & 31;
    const int bz = blockIdx.z;
    const int b = bz >> 2, n = bz & 3;
    const int p0 = blockIdx.y * 8;
    const int a0 = blockIdx.x * 16;

    const int mwarp = (wid & 3) * 32;
    const int nwarp = (wid >> 2) * 64;

    // producer group: wid>>2 -> warps {4g..4g+3} = one per SMSP
    const int group = wid >> 2;

    // epilogue tables
    if (tid < 256) {
        bmid_s[tid] = bmid[n * H_ + tid];
        wout_s[tid] = Wout[n * H_ + tid];
    }
#pragma unroll
    for (int q = 0; q < 2; q++) {
        const int i = q * NTHR + tid;
        wtail_s[i] = Wmid[(n * (H_ + NC_) + H_ + (i >> 8)) * H_ + (i & 255)];
    }

    // coalesced build mapping: within the 128-thread group, 4 lanes per row,
    // 4 passes of 32 rows. Each pass: lane covers 4 consecutive k.
    const int gt = (wid & 3) * 32 + lane;   // 0..127 within group
    const int brow0 = gt >> 2;              // row block 0..31 (pass adds 32*pp)
    const int bk4 = (gt & 3) * 4;           // k offset within 16-k quarter
    const float* hp_base = g_hp + (b * L_) * H_;
    const float* ha_base = g_ha + (b * L_ * NC_ + n) * H_;

    // lane-constant ldmatrix address offsets
    const uint32_t a_off = (uint32_t)((mwarp + (lane & 15)) * ROWB + ((lane >> 4) << 4));
    const uint32_t b_off = (uint32_t)((nwarp + (lane & 7) + ((lane & 16) ? 8 : 0)) * ROWB
                                      + ((lane & 8) ? 16 : 0));

    // build 16 k-values of chunk c at k-offset qoff into buffer buf
    // (group-collective: 128 threads, 4 passes x 32 rows x 4 lanes/row)
    auto buildX_part = [&](int c, int buf, int qoff) {
        const int kg = c * KCH + qoff + bk4;     // global k for this lane
#pragma unroll
        for (int pp = 0; pp < 4; pp++) {
            const int row = pp * 32 + brow0;     // 0..127
            const int p = p0 + (row >> 4);
            const int a = a0 + (row & 15);
            const float4 u = *(const float4*)(hp_base + p * H_ + kg);
            const float4 v = *(const float4*)(ha_base + a * (NC_ * H_) + kg);
            const float x0 = htanh(u.x + v.x);
            const float x1 = htanh(u.y + v.y);
            const float x2 = htanh(u.z + v.z);
            const float x3 = htanh(u.w + v.w);
            const uint32_t lo = f16pack(x0, x1);
            const uint32_t hi = f16pack(x2, x3);
            sts64(base + OXB(buf) + (uint32_t)(row * ROWB + (qoff + bk4) * 2),
                  lo, hi);
        }
    };

    auto copyW = [&](int c, int buf) {
        const char* src = g_w_img + (size_t)(n * NCHUNK + c) * WIMG_BYTES;
        const uint32_t dst = base + OWB(buf);
#pragma unroll
        for (int i = 0; i < 4; i++) {
            const int e = i * NTHR + tid;
            cp_async16(dst + e * 16, src + (size_t)e * 16);
        }
        // remainder: 2304 16B-chunks total, 2048 done above
        if (tid < 256) {
            const int e = 4 * NTHR + tid;
            cp_async16(dst + e * 16, src + (size_t)e * 16);
        }
        cp_commit();
    };

    float acc[2][8][4];
#pragma unroll
    for (int t = 0; t < 2; t++)
#pragma unroll
        for (int q = 0; q < 8; q++)
#pragma unroll
            for (int r = 0; r < 4; r++) acc[t][q][r] = 0.0f;

    // one k16-step: 16 independent MMAs
    auto mma_ks = [&](int ks, uint32_t xb, uint32_t wb) {
        uint32_t A0[4], A1[4], BH[4][4];
        const uint32_t kb = (uint32_t)(ks * 32);
        ldsm4(A0, xb + a_off + kb);
        ldsm4(A1, xb + a_off + 16 * ROWB + kb);
#pragma unroll
        for (int q = 0; q < 4; q++)
            ldsm4(BH[q], wb + b_off + q * 16 * ROWB + kb);
#pragma unroll
        for (int q2 = 0; q2 < 8; q2++) {
            const uint32_t* bq = &BH[q2 >> 1][(q2 & 1) * 2];
            mma16816(acc[0][q2], A0, bq);
            mma16816(acc[1][q2], A1, bq);
        }
    };

    // ---- prologue: each group builds its quarter of chunk 0 ----
    copyW(0, 0);
    buildX_part(0, 0, group * 16);
    cp_wait_all();
    __syncthreads();

#pragma unroll 1
    for (int c = 0; c < NCHUNK; c++) {
        const int cur = c & 1;
        const uint32_t xb = base + OXB(cur);
        const uint32_t wb = base + OWB(cur);
        const bool more = (c < NCHUNK - 1);
        if (more) copyW(c + 1, cur ^ 1);
        mma_ks(0, xb, wb);
        if (more && group == 0) buildX_part(c + 1, cur ^ 1, 0);
        mma_ks(1, xb, wb);
        if (more && group == 1) buildX_part(c + 1, cur ^ 1, 16);
        if (more && group == 3) buildX_part(c + 1, cur ^ 1, 48);
        mma_ks(2, xb, wb);
        if (more && group == 2) buildX_part(c + 1, cur ^ 1, 32);
        mma_ks(3, xb, wb);
        if (more) {
            cp_wait_all();
            __syncthreads();
        }
    }

    // ---- epilogue: +bs-tail +bmid, tanh, dot Wout, reduce over N ----
    const int g = lane >> 2;
    float bsv[2][2][4];
#pragma unroll
    for (int t = 0; t < 2; t++)
#pragma unroll
        for (int h = 0; h < 2; h++) {
            const int row = mwarp + t * 16 + g + h * 8;
            const float* bsp = bscore
                + ((b * L_ + p0 + (row >> 4)) * NC_) * L_ + a0 + (row & 15);
#pragma unroll
            for (int ct = 0; ct < 4; ct++) bsv[t][h][ct] = bsp[ct * L_];
        }

    float part[2][2] = {{0.0f, 0.0f}, {0.0f, 0.0f}};
#pragma unroll
    for (int q2 = 0; q2 < 8; q2++) {
        const int j0 = nwarp + q2 * 8 + (lane & 3) * 2;
        const float bm0 = bmid_s[j0], bm1 = bmid_s[j0 + 1];
        const float wo0 = wout_s[j0], wo1 = wout_s[j0 + 1];
        float wt0[4], wt1[4];
#pragma unroll
        for (int ct = 0; ct < 4; ct++) {
            wt0[ct] = wtail_s[ct * 256 + j0];
            wt1[ct] = wtail_s[ct * 256 + j0 + 1];
        }
#pragma unroll
        for (int t = 0; t < 2; t++)
#pragma unroll
            for (int h = 0; h < 2; h++) {
                float v0 = acc[t][q2][h * 2 + 0] + bm0;
                float v1 = acc[t][q2][h * 2 + 1] + bm1;
#pragma unroll
                for (int ct = 0; ct < 4; ct++) {
                    v0 = fmaf(bsv[t][h][ct], wt0[ct], v0);
                    v1 = fmaf(bsv[t][h][ct], wt1[ct], v1);
                }
                part[t][h] = fmaf(htanh(v0), wo0, part[t][h]);
                part[t][h] = fmaf(htanh(v1), wo1, part[t][h]);
            }
    }
#pragma unroll
    for (int t = 0; t < 2; t++)
#pragma unroll
        for (int h = 0; h < 2; h++) {
            float v = part[t][h];
            v += __shfl_xor_sync(0xFFFFFFFFu, v, 1, 4);
            v += __shfl_xor_sync(0xFFFFFFFFu, v, 2, 4);
            if ((lane & 3) == 0) {
                const int row = mwarp + t * 16 + g + h * 8;
                part_s[row * 4 + (wid >> 2)] = v;
            }
        }
    __syncthreads();

    if (tid < 128) {
        const float s = part_s[tid * 4] + part_s[tid * 4 + 1]
                      + part_s[tid * 4 + 2] + part_s[tid * 4 + 3];
        const int p = p0 + (tid >> 4);
        const int a = a0 + (tid & 15);
        out[((b * L_ + p) * NC_ + n) * L_ + a] = s;
    }
}

// ---------------------------------------------------------------------------
// Launch
// ---------------------------------------------------------------------------
extern "C" void kernel_launch(void* const* d_in, const int* in_sizes, int n_in,
                              void* d_out, int out_size) {
    const float* seq    = (const float*)d_in[0];
    const float* bscore = (const float*)d_in[1];
    const float* Wp     = (const float*)d_in[2];
    const float* bp     = (const float*)d_in[3];
    const float* Wa     = (const float*)d_in[4];
    const float* ba     = (const float*)d_in[5];
    const float* Wmid   = (const float*)d_in[6];
    const float* bmid   = (const float*)d_in[7];
    const float* Wout   = (const float*)d_in[8];
    float* out = (float*)d_out;

    prep_kernel<<<PREP_BLOCKS, 256>>>(seq, Wp, bp, Wa, ba, Wmid);

    cudaFuncSetAttribute(refine_kernel,
                         cudaFuncAttributeMaxDynamicSharedMemorySize, SMEM_BYTES);
    refine_kernel<<<dim3(L_ / 16, L_ / 8, B_ * NC_), NTHR, SMEM_BYTES>>>(
        bscore, Wmid, bmid, Wout, out);
}

// round 14
// speedup vs baseline: 2.5654x; 1.1071x over previous
#include <cuda_runtime.h>
#include <cuda_fp16.h>
#include <cstdint>

// Problem constants (fixed by the dataset)
#define B_  2
#define L_  192
#define D_  768
#define NC_ 4
#define H_  256

#define KCH     64              // k per chunk in refine
#define NCHUNK  4               // K = 256 = 4 x 64 (bs tail folded into epilogue)
#define NTHR    256             // refine threads (8 warps), 2 CTAs/SM
#define ROWB    144             // padded row stride: 64 fp16 = 128B + 16B pad
#define MTILE   64              // block M tile (4 p-rows x 16 a-rows)

#define WIMG_BYTES (256 * ROWB) // one W image: 256 n-rows x 144B

// Refine SMEM layout (byte offsets into dynamic smem) -- 97KB => 2 CTAs/SM
#define OXB(buf)  ((buf) * 9216)             // X bufs (fp16, 64 rows)
#define OWB(buf)  (18432 + (buf) * 36864)    // W bufs (fp16, single image)
#define OBMID     92160
#define OWOUT     93184
#define OWTAIL    94208                       // float[4][256]
#define OPART     98304                       // float[64][4]
#define SMEM_BYTES 99328

#define PROJ_BLOCKS 120   // 6 m-tiles x 20 n-tiles
#define PREP_BLOCKS (PROJ_BLOCKS + 32)

// Scratch (no cudaMalloc allowed)
__device__ float g_hp[B_ * L_ * H_];                 // [B*L, H]
__device__ float g_ha[B_ * L_ * NC_ * H_];           // [B*L, NC*H]
__device__ __align__(16) char g_w_img[NC_ * NCHUNK * WIMG_BYTES];

// ---------------------------------------------------------------------------
// Helpers
// ---------------------------------------------------------------------------
__device__ __forceinline__ float htanh(float x) {
    float y;
    asm("tanh.approx.f32 %0, %1;" : "=f"(y) : "f"(x));
    return y;
}

__device__ __forceinline__ uint32_t f16pack(float a, float b) {
    const __half2 h = __floats2half2_rn(a, b);
    return *(const uint32_t*)&h;
}

__device__ __forceinline__ unsigned long long pack2(float x) {
    unsigned long long r;
    asm("mov.b64 %0, {%1, %1};" : "=l"(r) : "f"(x));
    return r;
}
__device__ __forceinline__ unsigned long long ffma2(unsigned long long a,
                                                    unsigned long long b,
                                                    unsigned long long c) {
    unsigned long long d;
    asm("fma.rn.f32x2 %0, %1, %2, %3;" : "=l"(d) : "l"(a), "l"(b), "l"(c));
    return d;
}
__device__ __forceinline__ void unpack2(unsigned long long v, float& lo, float& hi) {
    asm("mov.b64 {%0, %1}, %2;" : "=f"(lo), "=f"(hi) : "l"(v));
}

__device__ __forceinline__ void cp_async16(uint32_t smem, const void* gptr) {
    asm volatile("cp.async.cg.shared.global [%0], [%1], 16;" :: "r"(smem), "l"(gptr));
}
__device__ __forceinline__ void cp_commit() { asm volatile("cp.async.commit_group;"); }
__device__ __forceinline__ void cp_wait_all() { asm volatile("cp.async.wait_group 0;" ::: "memory"); }

__device__ __forceinline__ void sts64(uint32_t addr, uint32_t r0, uint32_t r1) {
    asm volatile("st.shared.v2.b32 [%0], {%1, %2};"
                 :: "r"(addr), "r"(r0), "r"(r1) : "memory");
}

__device__ __forceinline__ void ldsm4(uint32_t* r, uint32_t addr) {
    asm volatile("ldmatrix.sync.aligned.m8n8.x4.shared.b16 {%0,%1,%2,%3}, [%4];"
                 : "=r"(r[0]), "=r"(r[1]), "=r"(r[2]), "=r"(r[3]) : "r"(addr));
}

__device__ __forceinline__ void mma16816(float* d, const uint32_t* a, const uint32_t* b) {
    asm volatile("mma.sync.aligned.m16n8k16.row.col.f32.f16.f16.f32 "
                 "{%0,%1,%2,%3}, {%4,%5,%6,%7}, {%8,%9}, {%0,%1,%2,%3};"
                 : "+f"(d[0]), "+f"(d[1]), "+f"(d[2]), "+f"(d[3])
                 : "r"(a[0]), "r"(a[1]), "r"(a[2]), "r"(a[3]),
                   "r"(b[0]), "r"(b[1]));
}

// ---------------------------------------------------------------------------
// Kernel 1 (fused): proj (blocks 0..119) + wsplit (blocks 120..151)
// ---------------------------------------------------------------------------
__global__ __launch_bounds__(256) void prep_kernel(
    const float* __restrict__ seq,
    const float* __restrict__ Wp, const float* __restrict__ bp,
    const float* __restrict__ Wa, const float* __restrict__ ba,
    const float* __restrict__ Wmid)
{
    const int tid = threadIdx.x;
    const int bx = blockIdx.x;

    if (bx >= PROJ_BLOCKS) {
        // ---- wsplit: fp16 image, rows padded to 144B ----
        const int idx = bx - PROJ_BLOCKS;
        const int n = idx >> 3, c = (idx >> 1) & 3, half = idx & 1;
        const int j = tid;
        char* img = g_w_img + (size_t)(n * NCHUNK + c) * WIMG_BYTES;
#pragma unroll 1
        for (int kp = half * 16; kp < half * 16 + 16; kp++) {
            const int k0 = c * KCH + kp * 2;
            const float w0 = Wmid[(n * (H_ + NC_) + k0    ) * H_ + j];
            const float w1 = Wmid[(n * (H_ + NC_) + k0 + 1) * H_ + j];
            *(uint32_t*)(img + j * ROWB + kp * 4) = f16pack(w0, w1);
        }
        if (half == 0)
            *(uint4*)(img + j * ROWB + 128) = make_uint4(0, 0, 0, 0);
        return;
    }

    // ---- proj: tile 64x64, KC=32, double-buffered ----
    __shared__ __align__(16) float As[2][32][68];   // [buf][k][m] padded
    __shared__ __align__(16) float Bs[2][32][64];   // [buf][k][n]

    const int tx = tid & 15;
    const int ty = tid >> 4;
    const int m0 = (bx / 20) * 64;
    const int n0 = (bx % 20) * 64;

    const float* Wsrc;
    int ld, coff;
    if (n0 < H_) { Wsrc = Wp; ld = H_;        coff = n0; }
    else         { Wsrc = Wa; ld = NC_ * H_;  coff = n0 - H_; }

    const int lm = tid >> 3;
    const int lk = (tid & 7) * 4;

    auto copyB = [&](int kc, int buf) {
        const uint32_t dst = (uint32_t)__cvta_generic_to_shared(&Bs[buf][0][0]);
#pragma unroll
        for (int i = 0; i < 2; i++) {
            const int e = i * 256 + tid;
            const int row = e >> 4, c4 = e & 15;
            cp_async16(dst + (uint32_t)(row * 256 + c4 * 16),
                       Wsrc + (size_t)(kc + row) * ld + coff + c4 * 4);
        }
        cp_commit();
    };
    auto ldgA = [&](int kc, float4* a) {
        a[0] = *(const float4*)(seq + (size_t)(m0 + lm) * D_ + kc + lk);
        a[1] = *(const float4*)(seq + (size_t)(m0 + lm + 32) * D_ + kc + lk);
    };
    auto stsA = [&](const float4* a, int buf) {
#pragma unroll
        for (int j = 0; j < 4; j++) {
            As[buf][lk + j][lm] = ((const float*)&a[0])[j];
            As[buf][lk + j][lm + 32] = ((const float*)&a[1])[j];
        }
    };

    unsigned long long acc2[4][2];
#pragma unroll
    for (int i = 0; i < 4; i++) { acc2[i][0] = 0ull; acc2[i][1] = 0ull; }

    float4 areg[2];
    copyB(0, 0);
    ldgA(0, areg);
    stsA(areg, 0);
    cp_wait_all();
    __syncthreads();

#pragma unroll 1
    for (int c = 0; c < 24; c++) {
        const int buf = c & 1;
        if (c < 23) {
            copyB((c + 1) * 32, buf ^ 1);
            ldgA((c + 1) * 32, areg);
        }
#pragma unroll
        for (int k = 0; k < 32; k++) {
            const float4 a4 = *(const float4*)&As[buf][k][ty * 4];
            const ulonglong2 b2 = *(const ulonglong2*)&Bs[buf][k][tx * 4];
            const unsigned long long pa[4] = {pack2(a4.x), pack2(a4.y),
                                              pack2(a4.z), pack2(a4.w)};
#pragma unroll
            for (int i = 0; i < 4; i++) {
                acc2[i][0] = ffma2(pa[i], b2.x, acc2[i][0]);
                acc2[i][1] = ffma2(pa[i], b2.y, acc2[i][1]);
            }
        }
        if (c < 23) {
            stsA(areg, buf ^ 1);
            cp_wait_all();
            __syncthreads();
        }
    }

#pragma unroll
    for (int i = 0; i < 4; i++) {
        const int r = m0 + ty * 4 + i;
#pragma unroll
        for (int j = 0; j < 2; j++) {
            float lo, hi;
            unpack2(acc2[i][j], lo, hi);
            const int cg = n0 + tx * 4 + j * 2;
            if (cg < H_) {
                g_hp[r * H_ + cg] = lo + bp[cg];
                g_hp[r * H_ + cg + 1] = hi + bp[cg + 1];
            } else {
                const int c2 = cg - H_;
                g_ha[r * (NC_ * H_) + c2] = lo + ba[c2];
                g_ha[r * (NC_ * H_) + c2 + 1] = hi + ba[c2 + 1];
            }
        }
    }
}

// ---------------------------------------------------------------------------
// Kernel 2: refinement via mma.sync m16n8k16 fp16 (X and W single fp16).
// Block (b, n, 4p x 16a): D[64,256] = X[64,256] @ W[256,256] + bs-tail (epi).
// 256 threads = 8 warps, 2(M)x4(N), warp tile 32x64. SMEM 97KB => 2 CTAs/SM:
// the co-resident CTA fills barrier/build bubbles.
// ---------------------------------------------------------------------------
__global__ __launch_bounds__(NTHR, 2) void refine_kernel(
    const float* __restrict__ bscore,   // [B, L, NC, L]
    const float* __restrict__ Wmid,     // [NC, H+NC, H]
    const float* __restrict__ bmid,     // [NC, H]
    const float* __restrict__ Wout,     // [NC, H]
    float* __restrict__ out)            // [B, L, NC, L]
{
    extern __shared__ __align__(16) char sm[];
    const uint32_t base = (uint32_t)__cvta_generic_to_shared(sm);

    float* bmid_s  = (float*)(sm + OBMID);
    float* wout_s  = (float*)(sm + OWOUT);
    float* wtail_s = (float*)(sm + OWTAIL);  // [4][256]
    float* part_s  = (float*)(sm + OPART);   // [64][4]

    const int tid = threadIdx.x;
    const int wid = tid >> 5;
    const int lane = tid & 31;
    const int bz = blockIdx.z;
    const int b = bz >> 2, n = bz & 3;
    const int p0 = blockIdx.y * 4;
    const int a0 = blockIdx.x * 16;

    const int mwarp = (wid & 1) * 32;
    const int nwarp = (wid >> 1) * 64;

    // producer group: wid>>1 -> 4 groups of 2 warps
    const int group = wid >> 1;

    // epilogue tables
    bmid_s[tid] = bmid[n * H_ + tid];
    wout_s[tid] = Wout[n * H_ + tid];
#pragma unroll
    for (int q = 0; q < 4; q++) {
        const int i = q * NTHR + tid;
        wtail_s[i] = Wmid[(n * (H_ + NC_) + H_ + (i >> 8)) * H_ + (i & 255)];
    }

    // coalesced build mapping: group = 64 threads, 4 lanes per row,
    // 4 passes of 16 rows. Each lane covers 4 consecutive k.
    const int gt = (wid & 1) * 32 + lane;   // 0..63 within group
    const int brow0 = gt >> 2;              // 0..15 (pass adds 16*pp)
    const int bk4 = (gt & 3) * 4;
    const float* hp_base = g_hp + (b * L_) * H_;
    const float* ha_base = g_ha + (b * L_ * NC_ + n) * H_;

    // lane-constant ldmatrix address offsets
    const uint32_t a_off = (uint32_t)((mwarp + (lane & 15)) * ROWB + ((lane >> 4) << 4));
    const uint32_t b_off = (uint32_t)((nwarp + (lane & 7) + ((lane & 16) ? 8 : 0)) * ROWB
                                      + ((lane & 8) ? 16 : 0));

    // build 16 k-values of chunk c at k-offset qoff into buffer buf
    auto buildX_part = [&](int c, int buf, int qoff) {
        const int kg = c * KCH + qoff + bk4;
#pragma unroll
        for (int pp = 0; pp < 4; pp++) {
            const int row = pp * 16 + brow0;     // 0..63
            const int p = p0 + (row >> 4);
            const int a = a0 + (row & 15);
            const float4 u = *(const float4*)(hp_base + p * H_ + kg);
            const float4 v = *(const float4*)(ha_base + a * (NC_ * H_) + kg);
            const float x0 = htanh(u.x + v.x);
            const float x1 = htanh(u.y + v.y);
            const float x2 = htanh(u.z + v.z);
            const float x3 = htanh(u.w + v.w);
            sts64(base + OXB(buf) + (uint32_t)(row * ROWB + (qoff + bk4) * 2),
                  f16pack(x0, x1), f16pack(x2, x3));
        }
    };

    auto copyW = [&](int c, int buf) {
        const char* src = g_w_img + (size_t)(n * NCHUNK + c) * WIMG_BYTES;
        const uint32_t dst = base + OWB(buf);
#pragma unroll
        for (int i = 0; i < 9; i++) {
            const int e = i * NTHR + tid;           // 2304 x 16B
            cp_async16(dst + e * 16, src + (size_t)e * 16);
        }
        cp_commit();
    };

    float acc[2][8][4];
#pragma unroll
    for (int t = 0; t < 2; t++)
#pragma unroll
        for (int q = 0; q < 8; q++)
#pragma unroll
            for (int r = 0; r < 4; r++) acc[t][q][r] = 0.0f;

    // one k16-step: 16 independent MMAs
    auto mma_ks = [&](int ks, uint32_t xb, uint32_t wb) {
        uint32_t A0[4], A1[4], BH[4][4];
        const uint32_t kb = (uint32_t)(ks * 32);
        ldsm4(A0, xb + a_off + kb);
        ldsm4(A1, xb + a_off + 16 * ROWB + kb);
#pragma unroll
        for (int q = 0; q < 4; q++)
            ldsm4(BH[q], wb + b_off + q * 16 * ROWB + kb);
#pragma unroll
        for (int q2 = 0; q2 < 8; q2++) {
            const uint32_t* bq = &BH[q2 >> 1][(q2 & 1) * 2];
            mma16816(acc[0][q2], A0, bq);
            mma16816(acc[1][q2], A1, bq);
        }
    };

    // ---- prologue: each group builds its quarter of chunk 0 ----
    copyW(0, 0);
    buildX_part(0, 0, group * 16);
    cp_wait_all();
    __syncthreads();

#pragma unroll 1
    for (int c = 0; c < NCHUNK; c++) {
        const int cur = c & 1;
        const uint32_t xb = base + OXB(cur);
        const uint32_t wb = base + OWB(cur);
        const bool more = (c < NCHUNK - 1);
        if (more) copyW(c + 1, cur ^ 1);
        mma_ks(0, xb, wb);
        if (more && group == 0) buildX_part(c + 1, cur ^ 1, 0);
        mma_ks(1, xb, wb);
        if (more && group == 1) buildX_part(c + 1, cur ^ 1, 16);
        if (more && group == 3) buildX_part(c + 1, cur ^ 1, 48);
        mma_ks(2, xb, wb);
        if (more && group == 2) buildX_part(c + 1, cur ^ 1, 32);
        mma_ks(3, xb, wb);
        if (more) {
            cp_wait_all();
            __syncthreads();
        }
    }

    // ---- epilogue: +bs-tail +bmid, tanh, dot Wout, reduce over N ----
    const int g = lane >> 2;
    float bsv[2][2][4];
#pragma unroll
    for (int t = 0; t < 2; t++)
#pragma unroll
        for (int h = 0; h < 2; h++) {
            const int row = mwarp + t * 16 + g + h * 8;
            const float* bsp = bscore
                + ((b * L_ + p0 + (row >> 4)) * NC_) * L_ + a0 + (row & 15);
#pragma unroll
            for (int ct = 0; ct < 4; ct++) bsv[t][h][ct] = bsp[ct * L_];
        }

    float part[2][2] = {{0.0f, 0.0f}, {0.0f, 0.0f}};
#pragma unroll
    for (int q2 = 0; q2 < 8; q2++) {
        const int j0 = nwarp + q2 * 8 + (lane & 3) * 2;
        const float bm0 = bmid_s[j0], bm1 = bmid_s[j0 + 1];
        const float wo0 = wout_s[j0], wo1 = wout_s[j0 + 1];
        float wt0[4], wt1[4];
#pragma unroll
        for (int ct = 0; ct < 4; ct++) {
            wt0[ct] = wtail_s[ct * 256 + j0];
            wt1[ct] = wtail_s[ct * 256 + j0 + 1];
        }
#pragma unroll
        for (int t = 0; t < 2; t++)
#pragma unroll
            for (int h = 0; h < 2; h++) {
                float v0 = acc[t][q2][h * 2 + 0] + bm0;
                float v1 = acc[t][q2][h * 2 + 1] + bm1;
#pragma unroll
                for (int ct = 0; ct < 4; ct++) {
                    v0 = fmaf(bsv[t][h][ct], wt0[ct], v0);
                    v1 = fmaf(bsv[t][h][ct], wt1[ct], v1);
                }
                part[t][h] = fmaf(htanh(v0), wo0, part[t][h]);
                part[t][h] = fmaf(htanh(v1), wo1, part[t][h]);
            }
    }
#pragma unroll
    for (int t = 0; t < 2; t++)
#pragma unroll
        for (int h = 0; h < 2; h++) {
            float v = part[t][h];
            v += __shfl_xor_sync(0xFFFFFFFFu, v, 1, 4);
            v += __shfl_xor_sync(0xFFFFFFFFu, v, 2, 4);
            if ((lane & 3) == 0) {
                const int row = mwarp + t * 16 + g + h * 8;
                part_s[row * 4 + (wid >> 1)] = v;
            }
        }
    __syncthreads();

    if (tid < 64) {
        const float s = part_s[tid * 4] + part_s[tid * 4 + 1]
                      + part_s[tid * 4 + 2] + part_s[tid * 4 + 3];
        const int p = p0 + (tid >> 4);
        const int a = a0 + (tid & 15);
        out[((b * L_ + p) * NC_ + n) * L_ + a] = s;
    }
}

// ---------------------------------------------------------------------------
// Launch
// ---------------------------------------------------------------------------
extern "C" void kernel_launch(void* const* d_in, const int* in_sizes, int n_in,
                              void* d_out, int out_size) {
    const float* seq    = (const float*)d_in[0];
    const float* bscore = (const float*)d_in[1];
    const float* Wp     = (const float*)d_in[2];
    const float* bp     = (const float*)d_in[3];
    const float* Wa     = (const float*)d_in[4];
    const float* ba     = (const float*)d_in[5];
    const float* Wmid   = (const float*)d_in[6];
    const float* bmid   = (const float*)d_in[7];
    const float* Wout   = (const float*)d_in[8];
    float* out = (float*)d_out;

    prep_kernel<<<PREP_BLOCKS, 256>>>(seq, Wp, bp, Wa, ba, Wmid);

    cudaFuncSetAttribute(refine_kernel,
                         cudaFuncAttributeMaxDynamicSharedMemorySize, SMEM_BYTES);
    refine_kernel<<<dim3(L_ / 16, L_ / 4, B_ * NC_), NTHR, SMEM_BYTES>>>(
        bscore, Wmid, bmid, Wout, out);
}